// round 1
// baseline (speedup 1.0000x reference)
#include <cuda_runtime.h>
#include <math.h>

// Problem constants
#define Bc   4
#define Lc   4096
#define Dc   1024
#define Hc   16
#define Dhc  64
#define Mtot (Bc*Lc)        // 16384 rows
#define NC   32             // scan chunks per sequence
#define CHUNK (Lc/NC)       // 128

// Scratch (allocation-free rule: __device__ globals)
__device__ float g_q[Mtot*Dc];     // q, later overwritten with ret
__device__ float g_v[Mtot*Dc];     // v, later overwritten with z (LN*gate)
__device__ float g_g[Mtot*Dc];     // gate pre-activation
__device__ float g_chunkS[Bc*Hc*NC*Dhc];
__device__ float g_carry [Bc*Hc*NC*Dhc];

// ---------------------------------------------------------------------------
// SGEMM: C[m,n] = sum_k A[m,k] * W[n,k]   (A: MxK row-major, W: NxK row-major)
// M=16384, N=1024, K=1024. 128x128 block tile, BK=8, 8x8 per thread, 256 thr.
// ---------------------------------------------------------------------------
__global__ __launch_bounds__(256)
void sgemm_nt(const float* __restrict__ A, const float* __restrict__ W,
              float* __restrict__ C)
{
    const int K = Dc;
    const int N = Dc;

    __shared__ float As[8][132];   // [k][m], padded to kill store conflicts
    __shared__ float Bs[8][132];   // [k][n]

    const int bn  = blockIdx.x * 128;   // n offset
    const int bm  = blockIdx.y * 128;   // m offset
    const int tid = threadIdx.x;
    const int tx  = tid & 15;           // 0..15 -> n microtile
    const int ty  = tid >> 4;           // 0..15 -> m microtile

    const int arow = tid >> 1;          // 0..127
    const int ak4  = (tid & 1) * 4;     // 0 or 4

    const float* Aptr = A + (size_t)(bm + arow) * K + ak4;
    const float* Wptr = W + (size_t)(bn + arow) * K + ak4;

    float acc[8][8];
    #pragma unroll
    for (int i = 0; i < 8; i++)
        #pragma unroll
        for (int j = 0; j < 8; j++) acc[i][j] = 0.0f;

    for (int k0 = 0; k0 < K; k0 += 8) {
        float4 a4 = *(const float4*)(Aptr + k0);
        float4 b4 = *(const float4*)(Wptr + k0);

        __syncthreads();   // protect prior-iteration reads
        As[ak4+0][arow] = a4.x; As[ak4+1][arow] = a4.y;
        As[ak4+2][arow] = a4.z; As[ak4+3][arow] = a4.w;
        Bs[ak4+0][arow] = b4.x; Bs[ak4+1][arow] = b4.y;
        Bs[ak4+2][arow] = b4.z; Bs[ak4+3][arow] = b4.w;
        __syncthreads();

        #pragma unroll
        for (int k = 0; k < 8; k++) {
            float rm[8], rn[8];
            *(float4*)&rm[0] = *(const float4*)&As[k][ty*8];
            *(float4*)&rm[4] = *(const float4*)&As[k][ty*8+4];
            *(float4*)&rn[0] = *(const float4*)&Bs[k][tx*8];
            *(float4*)&rn[4] = *(const float4*)&Bs[k][tx*8+4];
            #pragma unroll
            for (int i = 0; i < 8; i++)
                #pragma unroll
                for (int j = 0; j < 8; j++)
                    acc[i][j] = fmaf(rm[i], rn[j], acc[i][j]);
        }
    }

    #pragma unroll
    for (int i = 0; i < 8; i++) {
        float* crow = C + (size_t)(bm + ty*8 + i) * N + bn + tx*8;
        *(float4*)(crow    ) = make_float4(acc[i][0], acc[i][1], acc[i][2], acc[i][3]);
        *(float4*)(crow + 4) = make_float4(acc[i][4], acc[i][5], acc[i][6], acc[i][7]);
    }
}

// ---------------------------------------------------------------------------
// Retention scan (chunked, 3 passes). lam_h = clamp(1 - 2^-beta_h, tiny, 1-1e-9)
// ---------------------------------------------------------------------------
__device__ __forceinline__ float lam_of(const float* beta, int h)
{
    float lam = 1.0f - exp2f(-beta[h]);
    lam = fmaxf(lam, 1.17549435e-38f);
    lam = fminf(lam, 1.0f);   // (1 - 1e-9) rounds to 1.0f in fp32
    return lam;
}

// Pass 1: per-chunk end state with zero initial condition.
// grid = B*H*NC blocks, 64 threads (dh)
__global__ __launch_bounds__(64)
void scan_pass1(const float* __restrict__ v, const float* __restrict__ beta)
{
    int blk = blockIdx.x;
    int c   = blk % NC;
    int bh  = blk / NC;            // b*H + h
    int h   = bh % Hc;
    int b   = bh / Hc;
    int dh  = threadIdx.x;

    float lam = lam_of(beta, h);
    size_t off = ((size_t)(b*Lc + c*CHUNK)) * Dc + h*Dhc + dh;

    float s = 0.0f;
    #pragma unroll 4
    for (int t = 0; t < CHUNK; t++) {
        s = fmaf(lam, s, v[off]);
        off += Dc;
    }
    g_chunkS[(size_t)(bh*NC + c)*Dhc + dh] = s;
}

// Pass 2: sequential combine of chunk states -> per-chunk carry-in.
// 4096 threads total.
__global__ __launch_bounds__(256)
void scan_pass2(const float* __restrict__ beta)
{
    int idx = blockIdx.x * blockDim.x + threadIdx.x;  // 0..4095
    int dh  = idx % Dhc;
    int bh  = idx / Dhc;
    int h   = bh % Hc;

    float lam = lam_of(beta, h);
    float lamP = lam;
    #pragma unroll
    for (int i = 0; i < 7; i++) lamP = lamP * lamP;   // lam^128

    float carry = 0.0f;
    for (int c = 0; c < NC; c++) {
        size_t pos = (size_t)(bh*NC + c)*Dhc + dh;
        g_carry[pos] = carry;
        carry = fmaf(lamP, carry, g_chunkS[pos]);
    }
}

// Pass 3: full local scan with carry-in, fused with ret = q * s.
// Writes ret into the q buffer (element read-then-write, safe).
__global__ __launch_bounds__(64)
void scan_pass3(const float* __restrict__ v, float* __restrict__ q,
                const float* __restrict__ beta)
{
    int blk = blockIdx.x;
    int c   = blk % NC;
    int bh  = blk / NC;
    int h   = bh % Hc;
    int b   = bh / Hc;
    int dh  = threadIdx.x;

    float lam = lam_of(beta, h);
    size_t off = ((size_t)(b*Lc + c*CHUNK)) * Dc + h*Dhc + dh;

    float s = g_carry[(size_t)(bh*NC + c)*Dhc + dh];
    #pragma unroll 4
    for (int t = 0; t < CHUNK; t++) {
        s = fmaf(lam, s, v[off]);
        q[off] = q[off] * s;
        off += Dc;
    }
}

// ---------------------------------------------------------------------------
// Fused LayerNorm(ret) * SiLU(gate) -> z. One block per row (16384 rows).
// ---------------------------------------------------------------------------
__global__ __launch_bounds__(256)
void ln_gate_kernel(const float* __restrict__ ret, const float* __restrict__ gate,
                    const float* __restrict__ gamma, const float* __restrict__ lbeta,
                    float* __restrict__ z)
{
    const size_t row = blockIdx.x;
    const int tid = threadIdx.x;

    const float4 r = ((const float4*)(ret  + row*Dc))[tid];
    const float4 g = ((const float4*)(gate + row*Dc))[tid];

    float s  = r.x + r.y + r.z + r.w;
    float ss = r.x*r.x + r.y*r.y + r.z*r.z + r.w*r.w;

    #pragma unroll
    for (int o = 16; o > 0; o >>= 1) {
        s  += __shfl_xor_sync(0xffffffffu, s,  o);
        ss += __shfl_xor_sync(0xffffffffu, ss, o);
    }
    __shared__ float shs[8], shq[8];
    if ((tid & 31) == 0) { shs[tid>>5] = s; shq[tid>>5] = ss; }
    __syncthreads();

    float tot = 0.0f, totq = 0.0f;
    #pragma unroll
    for (int i = 0; i < 8; i++) { tot += shs[i]; totq += shq[i]; }

    const float inv = 1.0f / (float)Dc;
    float mu   = tot * inv;
    float var  = totq * inv - mu * mu;
    float rstd = rsqrtf(var + 1e-5f);

    const float4 gm = ((const float4*)gamma)[tid];
    const float4 bt = ((const float4*)lbeta)[tid];

    float4 o;
    o.x = ((r.x - mu)*rstd*gm.x + bt.x) * (g.x / (1.0f + expf(-g.x)));
    o.y = ((r.y - mu)*rstd*gm.y + bt.y) * (g.y / (1.0f + expf(-g.y)));
    o.z = ((r.z - mu)*rstd*gm.z + bt.z) * (g.z / (1.0f + expf(-g.z)));
    o.w = ((r.w - mu)*rstd*gm.w + bt.w) * (g.w / (1.0f + expf(-g.w)));

    ((float4*)(z + row*Dc))[tid] = o;
}

// ---------------------------------------------------------------------------
// Launch
// ---------------------------------------------------------------------------
extern "C" void kernel_launch(void* const* d_in, const int* in_sizes, int n_in,
                              void* d_out, int out_size)
{
    const float* x      = (const float*)d_in[0];
    const float* Wq     = (const float*)d_in[1];
    const float* Wv     = (const float*)d_in[2];
    const float* Wo     = (const float*)d_in[3];
    const float* Wg     = (const float*)d_in[4];
    const float* beta   = (const float*)d_in[5];
    const float* gamma  = (const float*)d_in[6];
    const float* lbeta  = (const float*)d_in[7];
    float* out          = (float*)d_out;

    float *q, *v, *g;
    cudaGetSymbolAddress((void**)&q, g_q);
    cudaGetSymbolAddress((void**)&v, g_v);
    cudaGetSymbolAddress((void**)&g, g_g);

    dim3 ggrid(Dc/128, Mtot/128);   // (8, 128)
    sgemm_nt<<<ggrid, 256>>>(x, Wq, q);
    sgemm_nt<<<ggrid, 256>>>(x, Wv, v);
    sgemm_nt<<<ggrid, 256>>>(x, Wg, g);

    scan_pass1<<<Bc*Hc*NC, 64>>>(v, beta);
    scan_pass2<<<(Bc*Hc*Dhc)/256, 256>>>(beta);
    scan_pass3<<<Bc*Hc*NC, 64>>>(v, q, beta);   // q now holds ret

    ln_gate_kernel<<<Mtot, 256>>>(q, g, gamma, lbeta, v);  // v now holds z

    sgemm_nt<<<ggrid, 256>>>(v, Wo, out);
}

// round 3
// speedup vs baseline: 2.3440x; 2.3440x over previous
#include <cuda_runtime.h>
#include <cuda_bf16.h>
#include <math.h>
#include <stdint.h>

// Problem constants
#define Bc   4
#define Lc   4096
#define Dc   1024
#define Hc   16
#define Dhc  64
#define Mtot (Bc*Lc)        // 16384 rows
#define NC   32             // scan chunks per sequence
#define CHUNK (Lc/NC)       // 128

// GEMM tiling (mma.sync path)
#define MT 128
#define NT 128
#define KT 32               // k per stage
#define NKC (Dc/KT)         // 32 k-chunks
#define TILE_BYTES (MT*KT*2)        // 8192 per operand tile
#define OFF_AH 0
#define OFF_AL (1*TILE_BYTES)
#define OFF_WH (2*TILE_BYTES)
#define OFF_WL (3*TILE_BYTES)
#define STAGE_BYTES (4*TILE_BYTES)  // 32768
#define NSTAGE 3
#define GEMM_SMEM (NSTAGE*STAGE_BYTES)

// ---------------------------------------------------------------------------
// Scratch (__device__ globals per allocation-free rule)
// ---------------------------------------------------------------------------
__device__ float g_q[Mtot*Dc];                 // q -> ret
__device__ float g_v[Mtot*Dc];                 // v
__device__ float g_g[Mtot*Dc];                 // gate pre-activation
__device__ float g_chunkS[Bc*Hc*NC*Dhc];
__device__ float g_carry [Bc*Hc*NC*Dhc];
__device__ __nv_bfloat16 g_xh[Mtot*Dc];
__device__ __nv_bfloat16 g_xl[Mtot*Dc];
__device__ __nv_bfloat16 g_zh[Mtot*Dc];
__device__ __nv_bfloat16 g_zl[Mtot*Dc];
__device__ __nv_bfloat16 g_wh[4*Dc*Dc];        // Wq,Wv,Wg,Wo hi
__device__ __nv_bfloat16 g_wl[4*Dc*Dc];        // lo

// ---------------------------------------------------------------------------
// PTX helpers (base ISA only: cp.async, ldmatrix, mma.sync — no tcgen05)
// ---------------------------------------------------------------------------
__device__ __forceinline__ uint32_t smem_to_u32(const void* p) {
    uint32_t a;
    asm("{ .reg .u64 t; cvta.to.shared.u64 t, %1; cvt.u32.u64 %0, t; }" : "=r"(a) : "l"(p));
    return a;
}

#define CP16(dst, src) \
    asm volatile("cp.async.cg.shared.global [%0], [%1], 16;" :: "r"(dst), "l"(src) : "memory")

__device__ __forceinline__ void ldsm_x4(uint32_t (&r)[4], uint32_t addr) {
    asm volatile("ldmatrix.sync.aligned.m8n8.x4.shared.b16 {%0,%1,%2,%3}, [%4];"
        : "=r"(r[0]), "=r"(r[1]), "=r"(r[2]), "=r"(r[3]) : "r"(addr));
}

__device__ __forceinline__ void mma16816(float (&c)[4], const uint32_t (&a)[4],
                                         uint32_t b0, uint32_t b1) {
    asm volatile("mma.sync.aligned.m16n8k16.row.col.f32.bf16.bf16.f32 "
        "{%0,%1,%2,%3}, {%4,%5,%6,%7}, {%8,%9}, {%0,%1,%2,%3};"
        : "+f"(c[0]), "+f"(c[1]), "+f"(c[2]), "+f"(c[3])
        : "r"(a[0]), "r"(a[1]), "r"(a[2]), "r"(a[3]), "r"(b0), "r"(b1));
}

// ---------------------------------------------------------------------------
// Split fp32 -> (hi bf16, lo bf16)
// ---------------------------------------------------------------------------
__global__ __launch_bounds__(256)
void split_kernel(const float* __restrict__ s, __nv_bfloat16* __restrict__ hi,
                  __nv_bfloat16* __restrict__ lo, int n4)
{
    int i = blockIdx.x * 256 + threadIdx.x;
    if (i >= n4) return;
    float4 f = ((const float4*)s)[i];
    __nv_bfloat16 h0 = __float2bfloat16(f.x);
    __nv_bfloat16 h1 = __float2bfloat16(f.y);
    __nv_bfloat16 h2 = __float2bfloat16(f.z);
    __nv_bfloat16 h3 = __float2bfloat16(f.w);
    __nv_bfloat16 l0 = __float2bfloat16(f.x - __bfloat162float(h0));
    __nv_bfloat16 l1 = __float2bfloat16(f.y - __bfloat162float(h1));
    __nv_bfloat16 l2 = __float2bfloat16(f.z - __bfloat162float(h2));
    __nv_bfloat16 l3 = __float2bfloat16(f.w - __bfloat162float(h3));
    __nv_bfloat162 hp0(h0, h1), hp1(h2, h3), lp0(l0, l1), lp1(l2, l3);
    uint2 hv, lv;
    hv.x = *(uint32_t*)&hp0; hv.y = *(uint32_t*)&hp1;
    lv.x = *(uint32_t*)&lp0; lv.y = *(uint32_t*)&lp1;
    ((uint2*)hi)[i] = hv;
    ((uint2*)lo)[i] = lv;
}

// ---------------------------------------------------------------------------
// mma.sync GEMM: C[m,n] = sum_k A[m,k]*W[n,k], bf16x3 split, fp32 out.
// 128x128 CTA tile, 8 warps (32x64 each), K-chunk 32, 3-stage cp.async.
// ---------------------------------------------------------------------------
__global__ __launch_bounds__(256, 1)
void gemm_mma(const __nv_bfloat16* __restrict__ Ah, const __nv_bfloat16* __restrict__ Al,
              const __nv_bfloat16* __restrict__ Wh, const __nv_bfloat16* __restrict__ Wl,
              float* __restrict__ C)
{
    extern __shared__ char smem[];
    const uint32_t sbase = smem_to_u32(smem);
    const int tid  = threadIdx.x;
    const int lane = tid & 31;
    const int wid  = tid >> 5;
    const int wm   = wid & 3;        // warp row  (4 x 32 = 128 M)
    const int wn   = wid >> 2;       // warp col  (2 x 64 = 128 N)
    const int bn   = blockIdx.x * NT;
    const int bm   = blockIdx.y * MT;

    // cp.async mapping: idx -> (row, 16B-chunk); 512 chunks/tile, 2 per thread
    const int row0 = tid >> 2;            // 0..63
    const int ch0  = tid & 3;

    auto load_stage = [&](int st, int kc) {
        const uint32_t sb = sbase + (uint32_t)st * STAGE_BYTES;
        const int k0 = kc * KT;
        #pragma unroll
        for (int rep = 0; rep < 2; rep++) {
            int row = row0 + rep * 64;
            int ch  = ch0;
            uint32_t sw = (uint32_t)row * 64 + (uint32_t)((ch ^ (row & 3)) * 16);
            const __nv_bfloat16* pa = Ah + (size_t)(bm + row) * Dc + k0 + ch * 8;
            const __nv_bfloat16* pl = Al + (size_t)(bm + row) * Dc + k0 + ch * 8;
            const __nv_bfloat16* pw = Wh + (size_t)(bn + row) * Dc + k0 + ch * 8;
            const __nv_bfloat16* pq = Wl + (size_t)(bn + row) * Dc + k0 + ch * 8;
            CP16(sb + OFF_AH + sw, pa);
            CP16(sb + OFF_AL + sw, pl);
            CP16(sb + OFF_WH + sw, pw);
            CP16(sb + OFF_WL + sw, pq);
        }
        asm volatile("cp.async.commit_group;" ::: "memory");
    };

    float c[2][8][4];
    #pragma unroll
    for (int i = 0; i < 2; i++)
        #pragma unroll
        for (int j = 0; j < 8; j++)
            #pragma unroll
            for (int k = 0; k < 4; k++) c[i][j][k] = 0.0f;

    load_stage(0, 0);
    load_stage(1, 1);

    // Per-lane ldmatrix address components
    // A (x4, m16k16): row_in_tile = mi*16 + (lane&15); kchunk = kstep*2 + (lane>>4)
    const int a_r  = lane & 15;
    const int a_kc = lane >> 4;
    // B (x4, two n8k16 tiles): row = pair*16 + ((lane>>4)<<3) + (lane&7);
    //                          kchunk = kstep*2 + ((lane>>3)&1)
    const int b_r  = ((lane >> 4) << 3) + (lane & 7);
    const int b_kc = (lane >> 3) & 1;

    for (int kc = 0; kc < NKC; kc++) {
        const int st = kc % NSTAGE;
        asm volatile("cp.async.wait_group 1;" ::: "memory");
        __syncthreads();

        if (kc + 2 < NKC) load_stage((kc + 2) % NSTAGE, kc + 2);
        else asm volatile("cp.async.commit_group;" ::: "memory");

        const uint32_t sb = sbase + (uint32_t)st * STAGE_BYTES;

        #pragma unroll
        for (int ks = 0; ks < 2; ks++) {
            uint32_t ah[2][4], al[2][4];
            #pragma unroll
            for (int mi = 0; mi < 2; mi++) {
                int row = wm * 32 + mi * 16 + a_r;
                int kk  = ks * 2 + a_kc;
                uint32_t sw = (uint32_t)row * 64 + (uint32_t)(((kk ^ (row & 3)) & 3) * 16);
                ldsm_x4(ah[mi], sb + OFF_AH + sw);
                ldsm_x4(al[mi], sb + OFF_AL + sw);
            }
            uint32_t bh[4][4], bl[4][4];
            #pragma unroll
            for (int pr = 0; pr < 4; pr++) {
                int row = wn * 64 + pr * 16 + b_r;
                int kk  = ks * 2 + b_kc;
                uint32_t sw = (uint32_t)row * 64 + (uint32_t)(((kk ^ (row & 3)) & 3) * 16);
                ldsm_x4(bh[pr], sb + OFF_WH + sw);
                ldsm_x4(bl[pr], sb + OFF_WL + sw);
            }
            #pragma unroll
            for (int mi = 0; mi < 2; mi++) {
                #pragma unroll
                for (int pr = 0; pr < 4; pr++) {
                    mma16816(c[mi][2*pr+0], ah[mi], bh[pr][0], bh[pr][1]);
                    mma16816(c[mi][2*pr+1], ah[mi], bh[pr][2], bh[pr][3]);
                    mma16816(c[mi][2*pr+0], ah[mi], bl[pr][0], bl[pr][1]);
                    mma16816(c[mi][2*pr+1], ah[mi], bl[pr][2], bl[pr][3]);
                    mma16816(c[mi][2*pr+0], al[mi], bh[pr][0], bh[pr][1]);
                    mma16816(c[mi][2*pr+1], al[mi], bh[pr][2], bh[pr][3]);
                }
            }
        }
    }

    // Epilogue: c[mi][ni] tile -> rows (lane>>2, +8), cols (lane&3)*2
    const int er = lane >> 2;
    const int ec = (lane & 3) * 2;
    #pragma unroll
    for (int mi = 0; mi < 2; mi++) {
        #pragma unroll
        for (int ni = 0; ni < 8; ni++) {
            size_t r0g = (size_t)(bm + wm * 32 + mi * 16 + er);
            size_t cg  = (size_t)(bn + wn * 64 + ni * 8 + ec);
            float2* p0 = (float2*)(C + r0g * Dc + cg);
            float2* p1 = (float2*)(C + (r0g + 8) * Dc + cg);
            *p0 = make_float2(c[mi][ni][0], c[mi][ni][1]);
            *p1 = make_float2(c[mi][ni][2], c[mi][ni][3]);
        }
    }
}

// ---------------------------------------------------------------------------
// Retention scan
// ---------------------------------------------------------------------------
__device__ __forceinline__ float lam_of(const float* beta, int h)
{
    float lam = 1.0f - exp2f(-beta[h]);
    lam = fmaxf(lam, 1.17549435e-38f);
    lam = fminf(lam, 1.0f);
    return lam;
}

__global__ __launch_bounds__(64)
void scan_pass1(const float* __restrict__ v, const float* __restrict__ beta)
{
    int blk = blockIdx.x;
    int cc  = blk % NC;
    int bh  = blk / NC;
    int h   = bh % Hc;
    int b   = bh / Hc;
    int dh  = threadIdx.x;

    float lam = lam_of(beta, h);
    size_t off = ((size_t)(b*Lc + cc*CHUNK)) * Dc + h*Dhc + dh;

    float s = 0.0f;
    #pragma unroll 4
    for (int t = 0; t < CHUNK; t++) {
        s = fmaf(lam, s, v[off]);
        off += Dc;
    }
    g_chunkS[(size_t)(bh*NC + cc)*Dhc + dh] = s;
}

__global__ __launch_bounds__(256)
void scan_pass2(const float* __restrict__ beta)
{
    int idx = blockIdx.x * blockDim.x + threadIdx.x;
    int dh  = idx % Dhc;
    int bh  = idx / Dhc;
    int h   = bh % Hc;

    float lam = lam_of(beta, h);
    float lamP = lam;
    #pragma unroll
    for (int i = 0; i < 7; i++) lamP = lamP * lamP;   // lam^128

    float carry = 0.0f;
    for (int cc = 0; cc < NC; cc++) {
        size_t pos = (size_t)(bh*NC + cc)*Dhc + dh;
        g_carry[pos] = carry;
        carry = fmaf(lamP, carry, g_chunkS[pos]);
    }
}

__global__ __launch_bounds__(64)
void scan_pass3(const float* __restrict__ v, float* __restrict__ q,
                const float* __restrict__ beta)
{
    int blk = blockIdx.x;
    int cc  = blk % NC;
    int bh  = blk / NC;
    int h   = bh % Hc;
    int b   = bh / Hc;
    int dh  = threadIdx.x;

    float lam = lam_of(beta, h);
    size_t off = ((size_t)(b*Lc + cc*CHUNK)) * Dc + h*Dhc + dh;

    float s = g_carry[(size_t)(bh*NC + cc)*Dhc + dh];
    #pragma unroll 4
    for (int t = 0; t < CHUNK; t++) {
        s = fmaf(lam, s, v[off]);
        q[off] = q[off] * s;
        off += Dc;
    }
}

// ---------------------------------------------------------------------------
// Fused LayerNorm(ret) * SiLU(gate) -> (zh, zl) bf16 split
// ---------------------------------------------------------------------------
__global__ __launch_bounds__(256)
void ln_gate_kernel(const float* __restrict__ ret, const float* __restrict__ gate,
                    const float* __restrict__ gamma, const float* __restrict__ lbeta,
                    __nv_bfloat16* __restrict__ zh, __nv_bfloat16* __restrict__ zl)
{
    const size_t row = blockIdx.x;
    const int tid = threadIdx.x;

    const float4 r = ((const float4*)(ret  + row*Dc))[tid];
    const float4 g = ((const float4*)(gate + row*Dc))[tid];

    float s  = r.x + r.y + r.z + r.w;
    float ss = r.x*r.x + r.y*r.y + r.z*r.z + r.w*r.w;

    #pragma unroll
    for (int o = 16; o > 0; o >>= 1) {
        s  += __shfl_xor_sync(0xffffffffu, s,  o);
        ss += __shfl_xor_sync(0xffffffffu, ss, o);
    }
    __shared__ float shs[8], shq[8];
    if ((tid & 31) == 0) { shs[tid>>5] = s; shq[tid>>5] = ss; }
    __syncthreads();

    float tot = 0.0f, totq = 0.0f;
    #pragma unroll
    for (int i = 0; i < 8; i++) { tot += shs[i]; totq += shq[i]; }

    const float inv = 1.0f / (float)Dc;
    float mu   = tot * inv;
    float var  = totq * inv - mu * mu;
    float rstd = rsqrtf(var + 1e-5f);

    const float4 gm = ((const float4*)gamma)[tid];
    const float4 bt = ((const float4*)lbeta)[tid];

    float4 o;
    o.x = ((r.x - mu)*rstd*gm.x + bt.x) * (g.x / (1.0f + expf(-g.x)));
    o.y = ((r.y - mu)*rstd*gm.y + bt.y) * (g.y / (1.0f + expf(-g.y)));
    o.z = ((r.z - mu)*rstd*gm.z + bt.z) * (g.z / (1.0f + expf(-g.z)));
    o.w = ((r.w - mu)*rstd*gm.w + bt.w) * (g.w / (1.0f + expf(-g.w)));

    __nv_bfloat16 h0 = __float2bfloat16(o.x), h1 = __float2bfloat16(o.y);
    __nv_bfloat16 h2 = __float2bfloat16(o.z), h3 = __float2bfloat16(o.w);
    __nv_bfloat16 l0 = __float2bfloat16(o.x - __bfloat162float(h0));
    __nv_bfloat16 l1 = __float2bfloat16(o.y - __bfloat162float(h1));
    __nv_bfloat16 l2 = __float2bfloat16(o.z - __bfloat162float(h2));
    __nv_bfloat16 l3 = __float2bfloat16(o.w - __bfloat162float(h3));
    __nv_bfloat162 hp0(h0, h1), hp1(h2, h3), lp0(l0, l1), lp1(l2, l3);
    uint2 hv, lv;
    hv.x = *(uint32_t*)&hp0; hv.y = *(uint32_t*)&hp1;
    lv.x = *(uint32_t*)&lp0; lv.y = *(uint32_t*)&lp1;
    ((uint2*)(zh + row*Dc))[tid] = hv;
    ((uint2*)(zl + row*Dc))[tid] = lv;
}

// ---------------------------------------------------------------------------
// Launch
// ---------------------------------------------------------------------------
extern "C" void kernel_launch(void* const* d_in, const int* in_sizes, int n_in,
                              void* d_out, int out_size)
{
    const float* x      = (const float*)d_in[0];
    const float* Wq     = (const float*)d_in[1];
    const float* Wv     = (const float*)d_in[2];
    const float* Wo     = (const float*)d_in[3];
    const float* Wg     = (const float*)d_in[4];
    const float* beta   = (const float*)d_in[5];
    const float* gamma  = (const float*)d_in[6];
    const float* lbeta  = (const float*)d_in[7];
    float* out          = (float*)d_out;

    float *q, *v, *g;
    __nv_bfloat16 *xh, *xl, *zh, *zl, *wh, *wl;
    cudaGetSymbolAddress((void**)&q, g_q);
    cudaGetSymbolAddress((void**)&v, g_v);
    cudaGetSymbolAddress((void**)&g, g_g);
    cudaGetSymbolAddress((void**)&xh, g_xh);
    cudaGetSymbolAddress((void**)&xl, g_xl);
    cudaGetSymbolAddress((void**)&zh, g_zh);
    cudaGetSymbolAddress((void**)&zl, g_zl);
    cudaGetSymbolAddress((void**)&wh, g_wh);
    cudaGetSymbolAddress((void**)&wl, g_wl);

    cudaFuncSetAttribute(gemm_mma, cudaFuncAttributeMaxDynamicSharedMemorySize, GEMM_SMEM);

    // Splits
    split_kernel<<<(Mtot*Dc/4 + 255)/256, 256>>>(x,  xh, xl, Mtot*Dc/4);
    split_kernel<<<(Dc*Dc/4 + 255)/256, 256>>>(Wq, wh + 0*(size_t)Dc*Dc, wl + 0*(size_t)Dc*Dc, Dc*Dc/4);
    split_kernel<<<(Dc*Dc/4 + 255)/256, 256>>>(Wv, wh + 1*(size_t)Dc*Dc, wl + 1*(size_t)Dc*Dc, Dc*Dc/4);
    split_kernel<<<(Dc*Dc/4 + 255)/256, 256>>>(Wg, wh + 2*(size_t)Dc*Dc, wl + 2*(size_t)Dc*Dc, Dc*Dc/4);
    split_kernel<<<(Dc*Dc/4 + 255)/256, 256>>>(Wo, wh + 3*(size_t)Dc*Dc, wl + 3*(size_t)Dc*Dc, Dc*Dc/4);

    dim3 ggrid(Dc/NT, Mtot/MT);   // (8, 128)
    gemm_mma<<<ggrid, 256, GEMM_SMEM>>>(xh, xl, wh + 0*(size_t)Dc*Dc, wl + 0*(size_t)Dc*Dc, q);
    gemm_mma<<<ggrid, 256, GEMM_SMEM>>>(xh, xl, wh + 1*(size_t)Dc*Dc, wl + 1*(size_t)Dc*Dc, v);
    gemm_mma<<<ggrid, 256, GEMM_SMEM>>>(xh, xl, wh + 2*(size_t)Dc*Dc, wl + 2*(size_t)Dc*Dc, g);

    scan_pass1<<<Bc*Hc*NC, 64>>>(v, beta);
    scan_pass2<<<(Bc*Hc*Dhc)/256, 256>>>(beta);
    scan_pass3<<<Bc*Hc*NC, 64>>>(v, q, beta);   // q now holds ret

    ln_gate_kernel<<<Mtot, 256>>>(q, g, gamma, lbeta, zh, zl);

    gemm_mma<<<ggrid, 256, GEMM_SMEM>>>(zh, zl, wh + 3*(size_t)Dc*Dc, wl + 3*(size_t)Dc*Dc, out);
}

// round 4
// speedup vs baseline: 2.4287x; 1.0362x over previous
#include <cuda_runtime.h>
#include <cuda_bf16.h>
#include <math.h>
#include <stdint.h>

// Problem constants
#define Bc   4
#define Lc   4096
#define Dc   1024
#define Hc   16
#define Dhc  64
#define Mtot (Bc*Lc)        // 16384 rows
#define NC   32             // scan chunks per sequence
#define CHUNK (Lc/NC)       // 128

// GEMM tiling (mma.sync path)
#define MT 128
#define NT 256
#define KT 32               // k per stage
#define NKC (Dc/KT)         // 32 k-chunks
#define A_TILE (MT*KT*2)            // 8192
#define W_TILE (NT*KT*2)            // 16384
#define OFF_AH 0
#define OFF_AL (A_TILE)
#define OFF_WH (2*A_TILE)
#define OFF_WL (2*A_TILE + W_TILE)
#define STAGE_BYTES (2*A_TILE + 2*W_TILE)  // 49152
#define NSTAGE 3
#define GEMM_SMEM (NSTAGE*STAGE_BYTES)     // 147456

// ---------------------------------------------------------------------------
// Scratch (__device__ globals per allocation-free rule)
// ---------------------------------------------------------------------------
__device__ float g_q[Mtot*Dc];                 // q -> ret
__device__ float g_v[Mtot*Dc];                 // v
__device__ float g_g[Mtot*Dc];                 // gate pre-activation
__device__ float g_chunkS[Bc*Hc*NC*Dhc];
__device__ float g_carry [Bc*Hc*NC*Dhc];
__device__ __nv_bfloat16 g_xh[Mtot*Dc];
__device__ __nv_bfloat16 g_xl[Mtot*Dc];
__device__ __nv_bfloat16 g_zh[Mtot*Dc];
__device__ __nv_bfloat16 g_zl[Mtot*Dc];
__device__ __nv_bfloat16 g_wh[4*Dc*Dc];        // Wq,Wv,Wg,Wo hi
__device__ __nv_bfloat16 g_wl[4*Dc*Dc];        // lo

// ---------------------------------------------------------------------------
// PTX helpers (base ISA only: cp.async, ldmatrix, mma.sync)
// ---------------------------------------------------------------------------
__device__ __forceinline__ uint32_t smem_to_u32(const void* p) {
    uint32_t a;
    asm("{ .reg .u64 t; cvta.to.shared.u64 t, %1; cvt.u32.u64 %0, t; }" : "=r"(a) : "l"(p));
    return a;
}

#define CP16(dst, src) \
    asm volatile("cp.async.cg.shared.global [%0], [%1], 16;" :: "r"(dst), "l"(src) : "memory")

__device__ __forceinline__ void ldsm_x4(uint32_t (&r)[4], uint32_t addr) {
    asm volatile("ldmatrix.sync.aligned.m8n8.x4.shared.b16 {%0,%1,%2,%3}, [%4];"
        : "=r"(r[0]), "=r"(r[1]), "=r"(r[2]), "=r"(r[3]) : "r"(addr));
}

__device__ __forceinline__ void mma16816(float (&c)[4], const uint32_t (&a)[4],
                                         uint32_t b0, uint32_t b1) {
    asm volatile("mma.sync.aligned.m16n8k16.row.col.f32.bf16.bf16.f32 "
        "{%0,%1,%2,%3}, {%4,%5,%6,%7}, {%8,%9}, {%0,%1,%2,%3};"
        : "+f"(c[0]), "+f"(c[1]), "+f"(c[2]), "+f"(c[3])
        : "r"(a[0]), "r"(a[1]), "r"(a[2]), "r"(a[3]), "r"(b0), "r"(b1));
}

// ---------------------------------------------------------------------------
// Split fp32 -> (hi bf16, lo bf16)
// ---------------------------------------------------------------------------
__global__ __launch_bounds__(256)
void split_kernel(const float* __restrict__ s, __nv_bfloat16* __restrict__ hi,
                  __nv_bfloat16* __restrict__ lo, int n4)
{
    int i = blockIdx.x * 256 + threadIdx.x;
    if (i >= n4) return;
    float4 f = ((const float4*)s)[i];
    __nv_bfloat16 h0 = __float2bfloat16(f.x);
    __nv_bfloat16 h1 = __float2bfloat16(f.y);
    __nv_bfloat16 h2 = __float2bfloat16(f.z);
    __nv_bfloat16 h3 = __float2bfloat16(f.w);
    __nv_bfloat16 l0 = __float2bfloat16(f.x - __bfloat162float(h0));
    __nv_bfloat16 l1 = __float2bfloat16(f.y - __bfloat162float(h1));
    __nv_bfloat16 l2 = __float2bfloat16(f.z - __bfloat162float(h2));
    __nv_bfloat16 l3 = __float2bfloat16(f.w - __bfloat162float(h3));
    __nv_bfloat162 hp0(h0, h1), hp1(h2, h3), lp0(l0, l1), lp1(l2, l3);
    uint2 hv, lv;
    hv.x = *(uint32_t*)&hp0; hv.y = *(uint32_t*)&hp1;
    lv.x = *(uint32_t*)&lp0; lv.y = *(uint32_t*)&lp1;
    ((uint2*)hi)[i] = hv;
    ((uint2*)lo)[i] = lv;
}

// ---------------------------------------------------------------------------
// mma.sync GEMM: C[m,n] = sum_k A[m,k]*W[n,k], bf16x3 split, fp32 out.
// 128x256 CTA tile, 8 warps (32x128 each), K-chunk 32, 3-stage cp.async.
// Up to 3 (W,C) pairs selected by blockIdx.z (fused q/v/g projections).
// ---------------------------------------------------------------------------
struct GemmArgs {
    const __nv_bfloat16* Ah;
    const __nv_bfloat16* Al;
    const __nv_bfloat16* Wh[3];
    const __nv_bfloat16* Wl[3];
    float* C[3];
};

__global__ __launch_bounds__(256, 1)
void gemm_mma(const GemmArgs args)
{
    extern __shared__ char smem[];
    const uint32_t sbase = smem_to_u32(smem);
    const int tid  = threadIdx.x;
    const int lane = tid & 31;
    const int wid  = tid >> 5;
    const int wm   = wid & 3;        // warp row  (4 x 32 = 128 M)
    const int wn   = wid >> 2;       // warp col  (2 x 128 = 256 N)
    const int bn   = blockIdx.x * NT;
    const int bm   = blockIdx.y * MT;
    const int z    = blockIdx.z;

    const __nv_bfloat16* __restrict__ Ah = args.Ah;
    const __nv_bfloat16* __restrict__ Al = args.Al;
    const __nv_bfloat16* __restrict__ Wh = args.Wh[z];
    const __nv_bfloat16* __restrict__ Wl = args.Wl[z];
    float* __restrict__ C = args.C[z];

    // cp.async mapping: thread -> (row = tid>>2 (+64 steps), ch = tid&3)
    const int row0 = tid >> 2;            // 0..63
    const int ch0  = tid & 3;

    auto load_stage = [&](int st, int kc) {
        const uint32_t sb = sbase + (uint32_t)st * STAGE_BYTES;
        const int k0 = kc * KT;
        const uint32_t swc = (uint32_t)((ch0 ^ (row0 & 3)) * 16);
        // A: 128 rows (2 reps)
        #pragma unroll
        for (int rep = 0; rep < 2; rep++) {
            int row = row0 + rep * 64;
            uint32_t sw = (uint32_t)row * 64 + swc;
            const __nv_bfloat16* pa = Ah + (size_t)(bm + row) * Dc + k0 + ch0 * 8;
            const __nv_bfloat16* pl = Al + (size_t)(bm + row) * Dc + k0 + ch0 * 8;
            CP16(sb + OFF_AH + sw, pa);
            CP16(sb + OFF_AL + sw, pl);
        }
        // W: 256 rows (4 reps)
        #pragma unroll
        for (int rep = 0; rep < 4; rep++) {
            int row = row0 + rep * 64;
            uint32_t sw = (uint32_t)row * 64 + swc;
            const __nv_bfloat16* pw = Wh + (size_t)(bn + row) * Dc + k0 + ch0 * 8;
            const __nv_bfloat16* pq = Wl + (size_t)(bn + row) * Dc + k0 + ch0 * 8;
            CP16(sb + OFF_WH + sw, pw);
            CP16(sb + OFF_WL + sw, pq);
        }
        asm volatile("cp.async.commit_group;" ::: "memory");
    };

    float c[2][16][4];
    #pragma unroll
    for (int i = 0; i < 2; i++)
        #pragma unroll
        for (int j = 0; j < 16; j++)
            #pragma unroll
            for (int k = 0; k < 4; k++) c[i][j][k] = 0.0f;

    load_stage(0, 0);
    load_stage(1, 1);

    // Per-lane ldmatrix address components
    const int a_r  = lane & 15;          // A m16k16: row within 16
    const int a_kc = lane >> 4;          // 16B k-chunk select
    const int b_r  = ((lane >> 4) << 3) + (lane & 7);  // B n16k16
    const int b_kc = (lane >> 3) & 1;

    for (int kc = 0; kc < NKC; kc++) {
        const int st = kc % NSTAGE;
        asm volatile("cp.async.wait_group 1;" ::: "memory");
        __syncthreads();

        if (kc + 2 < NKC) load_stage((kc + 2) % NSTAGE, kc + 2);
        else asm volatile("cp.async.commit_group;" ::: "memory");

        const uint32_t sb = sbase + (uint32_t)st * STAGE_BYTES;

        #pragma unroll
        for (int ks = 0; ks < 2; ks++) {
            uint32_t ah[2][4], al[2][4];
            #pragma unroll
            for (int mi = 0; mi < 2; mi++) {
                int row = wm * 32 + mi * 16 + a_r;
                int kk  = ks * 2 + a_kc;
                uint32_t sw = (uint32_t)row * 64 + (uint32_t)(((kk ^ (row & 3)) & 3) * 16);
                ldsm_x4(ah[mi], sb + OFF_AH + sw);
                ldsm_x4(al[mi], sb + OFF_AL + sw);
            }
            // Process B in two halves of 4 n16-tiles to bound live registers
            #pragma unroll
            for (int half = 0; half < 2; half++) {
                uint32_t bh[4][4], bl[4][4];
                #pragma unroll
                for (int p = 0; p < 4; p++) {
                    int pr  = half * 4 + p;
                    int row = wn * 128 + pr * 16 + b_r;
                    int kk  = ks * 2 + b_kc;
                    uint32_t sw = (uint32_t)row * 64 + (uint32_t)(((kk ^ (row & 3)) & 3) * 16);
                    ldsm_x4(bh[p], sb + OFF_WH + sw);
                    ldsm_x4(bl[p], sb + OFF_WL + sw);
                }
                #pragma unroll
                for (int mi = 0; mi < 2; mi++) {
                    #pragma unroll
                    for (int p = 0; p < 4; p++) {
                        int ni = (half * 4 + p) * 2;
                        mma16816(c[mi][ni+0], ah[mi], bh[p][0], bh[p][1]);
                        mma16816(c[mi][ni+1], ah[mi], bh[p][2], bh[p][3]);
                        mma16816(c[mi][ni+0], ah[mi], bl[p][0], bl[p][1]);
                        mma16816(c[mi][ni+1], ah[mi], bl[p][2], bl[p][3]);
                        mma16816(c[mi][ni+0], al[mi], bh[p][0], bh[p][1]);
                        mma16816(c[mi][ni+1], al[mi], bh[p][2], bh[p][3]);
                    }
                }
            }
        }
    }

    // Epilogue
    const int er = lane >> 2;
    const int ec = (lane & 3) * 2;
    #pragma unroll
    for (int mi = 0; mi < 2; mi++) {
        #pragma unroll
        for (int ni = 0; ni < 16; ni++) {
            size_t r0g = (size_t)(bm + wm * 32 + mi * 16 + er);
            size_t cg  = (size_t)(bn + wn * 128 + ni * 8 + ec);
            float2* p0 = (float2*)(C + r0g * Dc + cg);
            float2* p1 = (float2*)(C + (r0g + 8) * Dc + cg);
            *p0 = make_float2(c[mi][ni][0], c[mi][ni][1]);
            *p1 = make_float2(c[mi][ni][2], c[mi][ni][3]);
        }
    }
}

// ---------------------------------------------------------------------------
// Retention scan
// ---------------------------------------------------------------------------
__device__ __forceinline__ float lam_of(const float* beta, int h)
{
    float lam = 1.0f - exp2f(-beta[h]);
    lam = fmaxf(lam, 1.17549435e-38f);
    lam = fminf(lam, 1.0f);
    return lam;
}

__global__ __launch_bounds__(64)
void scan_pass1(const float* __restrict__ v, const float* __restrict__ beta)
{
    int blk = blockIdx.x;
    int cc  = blk % NC;
    int bh  = blk / NC;
    int h   = bh % Hc;
    int b   = bh / Hc;
    int dh  = threadIdx.x;

    float lam = lam_of(beta, h);
    size_t off = ((size_t)(b*Lc + cc*CHUNK)) * Dc + h*Dhc + dh;

    float s = 0.0f;
    #pragma unroll 4
    for (int t = 0; t < CHUNK; t++) {
        s = fmaf(lam, s, v[off]);
        off += Dc;
    }
    g_chunkS[(size_t)(bh*NC + cc)*Dhc + dh] = s;
}

__global__ __launch_bounds__(256)
void scan_pass2(const float* __restrict__ beta)
{
    int idx = blockIdx.x * blockDim.x + threadIdx.x;
    int dh  = idx % Dhc;
    int bh  = idx / Dhc;
    int h   = bh % Hc;

    float lam = lam_of(beta, h);
    float lamP = lam;
    #pragma unroll
    for (int i = 0; i < 7; i++) lamP = lamP * lamP;   // lam^128

    float carry = 0.0f;
    for (int cc = 0; cc < NC; cc++) {
        size_t pos = (size_t)(bh*NC + cc)*Dhc + dh;
        g_carry[pos] = carry;
        carry = fmaf(lamP, carry, g_chunkS[pos]);
    }
}

__global__ __launch_bounds__(64)
void scan_pass3(const float* __restrict__ v, float* __restrict__ q,
                const float* __restrict__ beta)
{
    int blk = blockIdx.x;
    int cc  = blk % NC;
    int bh  = blk / NC;
    int h   = bh % Hc;
    int b   = bh / Hc;
    int dh  = threadIdx.x;

    float lam = lam_of(beta, h);
    size_t off = ((size_t)(b*Lc + cc*CHUNK)) * Dc + h*Dhc + dh;

    float s = g_carry[(size_t)(bh*NC + cc)*Dhc + dh];
    #pragma unroll 4
    for (int t = 0; t < CHUNK; t++) {
        s = fmaf(lam, s, v[off]);
        q[off] = q[off] * s;
        off += Dc;
    }
}

// ---------------------------------------------------------------------------
// Fused LayerNorm(ret) * SiLU(gate) -> (zh, zl) bf16 split
// ---------------------------------------------------------------------------
__global__ __launch_bounds__(256)
void ln_gate_kernel(const float* __restrict__ ret, const float* __restrict__ gate,
                    const float* __restrict__ gamma, const float* __restrict__ lbeta,
                    __nv_bfloat16* __restrict__ zh, __nv_bfloat16* __restrict__ zl)
{
    const size_t row = blockIdx.x;
    const int tid = threadIdx.x;

    const float4 r = ((const float4*)(ret  + row*Dc))[tid];
    const float4 g = ((const float4*)(gate + row*Dc))[tid];

    float s  = r.x + r.y + r.z + r.w;
    float ss = r.x*r.x + r.y*r.y + r.z*r.z + r.w*r.w;

    #pragma unroll
    for (int o = 16; o > 0; o >>= 1) {
        s  += __shfl_xor_sync(0xffffffffu, s,  o);
        ss += __shfl_xor_sync(0xffffffffu, ss, o);
    }
    __shared__ float shs[8], shq[8];
    if ((tid & 31) == 0) { shs[tid>>5] = s; shq[tid>>5] = ss; }
    __syncthreads();

    float tot = 0.0f, totq = 0.0f;
    #pragma unroll
    for (int i = 0; i < 8; i++) { tot += shs[i]; totq += shq[i]; }

    const float inv = 1.0f / (float)Dc;
    float mu   = tot * inv;
    float var  = totq * inv - mu * mu;
    float rstd = rsqrtf(var + 1e-5f);

    const float4 gm = ((const float4*)gamma)[tid];
    const float4 bt = ((const float4*)lbeta)[tid];

    float4 o;
    o.x = ((r.x - mu)*rstd*gm.x + bt.x) * (g.x / (1.0f + expf(-g.x)));
    o.y = ((r.y - mu)*rstd*gm.y + bt.y) * (g.y / (1.0f + expf(-g.y)));
    o.z = ((r.z - mu)*rstd*gm.z + bt.z) * (g.z / (1.0f + expf(-g.z)));
    o.w = ((r.w - mu)*rstd*gm.w + bt.w) * (g.w / (1.0f + expf(-g.w)));

    __nv_bfloat16 h0 = __float2bfloat16(o.x), h1 = __float2bfloat16(o.y);
    __nv_bfloat16 h2 = __float2bfloat16(o.z), h3 = __float2bfloat16(o.w);
    __nv_bfloat16 l0 = __float2bfloat16(o.x - __bfloat162float(h0));
    __nv_bfloat16 l1 = __float2bfloat16(o.y - __bfloat162float(h1));
    __nv_bfloat16 l2 = __float2bfloat16(o.z - __bfloat162float(h2));
    __nv_bfloat16 l3 = __float2bfloat16(o.w - __bfloat162float(h3));
    __nv_bfloat162 hp0(h0, h1), hp1(h2, h3), lp0(l0, l1), lp1(l2, l3);
    uint2 hv, lv;
    hv.x = *(uint32_t*)&hp0; hv.y = *(uint32_t*)&hp1;
    lv.x = *(uint32_t*)&lp0; lv.y = *(uint32_t*)&lp1;
    ((uint2*)(zh + row*Dc))[tid] = hv;
    ((uint2*)(zl + row*Dc))[tid] = lv;
}

// ---------------------------------------------------------------------------
// Launch
// ---------------------------------------------------------------------------
extern "C" void kernel_launch(void* const* d_in, const int* in_sizes, int n_in,
                              void* d_out, int out_size)
{
    const float* x      = (const float*)d_in[0];
    const float* Wq     = (const float*)d_in[1];
    const float* Wv     = (const float*)d_in[2];
    const float* Wo     = (const float*)d_in[3];
    const float* Wg     = (const float*)d_in[4];
    const float* beta   = (const float*)d_in[5];
    const float* gamma  = (const float*)d_in[6];
    const float* lbeta  = (const float*)d_in[7];
    float* out          = (float*)d_out;

    float *q, *v, *g;
    __nv_bfloat16 *xh, *xl, *zh, *zl, *wh, *wl;
    cudaGetSymbolAddress((void**)&q, g_q);
    cudaGetSymbolAddress((void**)&v, g_v);
    cudaGetSymbolAddress((void**)&g, g_g);
    cudaGetSymbolAddress((void**)&xh, g_xh);
    cudaGetSymbolAddress((void**)&xl, g_xl);
    cudaGetSymbolAddress((void**)&zh, g_zh);
    cudaGetSymbolAddress((void**)&zl, g_zl);
    cudaGetSymbolAddress((void**)&wh, g_wh);
    cudaGetSymbolAddress((void**)&wl, g_wl);

    cudaFuncSetAttribute(gemm_mma, cudaFuncAttributeMaxDynamicSharedMemorySize, GEMM_SMEM);

    // Splits
    split_kernel<<<(Mtot*Dc/4 + 255)/256, 256>>>(x,  xh, xl, Mtot*Dc/4);
    split_kernel<<<(Dc*Dc/4 + 255)/256, 256>>>(Wq, wh + 0*(size_t)Dc*Dc, wl + 0*(size_t)Dc*Dc, Dc*Dc/4);
    split_kernel<<<(Dc*Dc/4 + 255)/256, 256>>>(Wv, wh + 1*(size_t)Dc*Dc, wl + 1*(size_t)Dc*Dc, Dc*Dc/4);
    split_kernel<<<(Dc*Dc/4 + 255)/256, 256>>>(Wg, wh + 2*(size_t)Dc*Dc, wl + 2*(size_t)Dc*Dc, Dc*Dc/4);
    split_kernel<<<(Dc*Dc/4 + 255)/256, 256>>>(Wo, wh + 3*(size_t)Dc*Dc, wl + 3*(size_t)Dc*Dc, Dc*Dc/4);

    // Fused q/v/g projection GEMMs (z-indexed)
    GemmArgs a1;
    a1.Ah = xh; a1.Al = xl;
    a1.Wh[0] = wh + 0*(size_t)Dc*Dc; a1.Wl[0] = wl + 0*(size_t)Dc*Dc; a1.C[0] = q;
    a1.Wh[1] = wh + 1*(size_t)Dc*Dc; a1.Wl[1] = wl + 1*(size_t)Dc*Dc; a1.C[1] = v;
    a1.Wh[2] = wh + 2*(size_t)Dc*Dc; a1.Wl[2] = wl + 2*(size_t)Dc*Dc; a1.C[2] = g;
    dim3 grid_qvg(Dc/NT, Mtot/MT, 3);   // (4, 128, 3)
    gemm_mma<<<grid_qvg, 256, GEMM_SMEM>>>(a1);

    scan_pass1<<<Bc*Hc*NC, 64>>>(v, beta);
    scan_pass2<<<(Bc*Hc*Dhc)/256, 256>>>(beta);
    scan_pass3<<<Bc*Hc*NC, 64>>>(v, q, beta);   // q now holds ret

    ln_gate_kernel<<<Mtot, 256>>>(q, g, gamma, lbeta, zh, zl);

    // Output GEMM
    GemmArgs a2;
    a2.Ah = zh; a2.Al = zl;
    a2.Wh[0] = wh + 3*(size_t)Dc*Dc; a2.Wl[0] = wl + 3*(size_t)Dc*Dc; a2.C[0] = out;
    a2.Wh[1] = a2.Wh[0]; a2.Wl[1] = a2.Wl[0]; a2.C[1] = out;
    a2.Wh[2] = a2.Wh[0]; a2.Wl[2] = a2.Wl[0]; a2.C[2] = out;
    dim3 grid_o(Dc/NT, Mtot/MT, 1);     // (4, 128, 1)
    gemm_mma<<<grid_o, 256, GEMM_SMEM>>>(a2);
}

// round 5
// speedup vs baseline: 2.6110x; 1.0750x over previous
#include <cuda_runtime.h>
#include <cuda_bf16.h>
#include <math.h>
#include <stdint.h>

// Problem constants
#define Bc   4
#define Lc   4096
#define Dc   1024
#define Hc   16
#define Dhc  64
#define Mtot (Bc*Lc)        // 16384 rows
#define NC   32             // scan chunks per sequence
#define CHUNK (Lc/NC)       // 128

// GEMM tiling (mma.sync path)
#define MT 128
#define NT 256
#define KT 32               // k per stage
#define NKC (Dc/KT)         // 32 k-chunks
#define A_TILE (MT*KT*2)            // 8192
#define W_TILE (NT*KT*2)            // 16384
#define OFF_AH 0
#define OFF_AL (A_TILE)
#define OFF_WH (2*A_TILE)
#define OFF_WL (2*A_TILE + W_TILE)
#define STAGE_BYTES (2*A_TILE + 2*W_TILE)  // 49152
#define NSTAGE 3
#define GEMM_SMEM (NSTAGE*STAGE_BYTES)     // 147456

// Conflict-free swizzle: 16B-chunk c (0..3) xored with (row>>1)&3.
// For any ldmatrix 8-row phase the 8 accessed 16B chunks cover all 32 banks.
#define SWZ(row, ch) ((uint32_t)(row) * 64 + (uint32_t)((((ch) ^ (((row) >> 1) & 3)) & 3) * 16))

// ---------------------------------------------------------------------------
// Scratch (__device__ globals per allocation-free rule)
// ---------------------------------------------------------------------------
__device__ float g_q[Mtot*Dc];                 // q -> ret
__device__ float g_v[Mtot*Dc];                 // v
__device__ float g_g[Mtot*Dc];                 // gate pre-activation
__device__ float g_chunkS[Bc*Hc*NC*Dhc];
__device__ float g_carry [Bc*Hc*NC*Dhc];
__device__ __nv_bfloat16 g_xh[Mtot*Dc];
__device__ __nv_bfloat16 g_xl[Mtot*Dc];
__device__ __nv_bfloat16 g_zh[Mtot*Dc];
__device__ __nv_bfloat16 g_zl[Mtot*Dc];
__device__ __nv_bfloat16 g_wh[4*Dc*Dc];        // Wq,Wv,Wg,Wo hi
__device__ __nv_bfloat16 g_wl[4*Dc*Dc];        // lo

// ---------------------------------------------------------------------------
// PTX helpers (base ISA only: cp.async, ldmatrix, mma.sync)
// ---------------------------------------------------------------------------
__device__ __forceinline__ uint32_t smem_to_u32(const void* p) {
    uint32_t a;
    asm("{ .reg .u64 t; cvta.to.shared.u64 t, %1; cvt.u32.u64 %0, t; }" : "=r"(a) : "l"(p));
    return a;
}

#define CP16(dst, src) \
    asm volatile("cp.async.cg.shared.global [%0], [%1], 16;" :: "r"(dst), "l"(src) : "memory")

__device__ __forceinline__ void ldsm_x4(uint32_t (&r)[4], uint32_t addr) {
    asm volatile("ldmatrix.sync.aligned.m8n8.x4.shared.b16 {%0,%1,%2,%3}, [%4];"
        : "=r"(r[0]), "=r"(r[1]), "=r"(r[2]), "=r"(r[3]) : "r"(addr));
}

__device__ __forceinline__ void mma16816(float (&c)[4], const uint32_t (&a)[4],
                                         uint32_t b0, uint32_t b1) {
    asm volatile("mma.sync.aligned.m16n8k16.row.col.f32.bf16.bf16.f32 "
        "{%0,%1,%2,%3}, {%4,%5,%6,%7}, {%8,%9}, {%0,%1,%2,%3};"
        : "+f"(c[0]), "+f"(c[1]), "+f"(c[2]), "+f"(c[3])
        : "r"(a[0]), "r"(a[1]), "r"(a[2]), "r"(a[3]), "r"(b0), "r"(b1));
}

// ---------------------------------------------------------------------------
// Split fp32 -> (hi bf16, lo bf16); batched over up to 5 tensors via blockIdx.y
// ---------------------------------------------------------------------------
struct SplitArgs {
    const float* src[5];
    __nv_bfloat16* hi[5];
    __nv_bfloat16* lo[5];
    int n4[5];
};

__global__ __launch_bounds__(256)
void split_kernel(const SplitArgs args)
{
    const int z = blockIdx.y;
    const float* s = args.src[z];
    __nv_bfloat16* hi = args.hi[z];
    __nv_bfloat16* lo = args.lo[z];
    const int n4 = args.n4[z];

    int i = blockIdx.x * 256 + threadIdx.x;
    if (i >= n4) return;
    float4 f = ((const float4*)s)[i];
    __nv_bfloat16 h0 = __float2bfloat16(f.x);
    __nv_bfloat16 h1 = __float2bfloat16(f.y);
    __nv_bfloat16 h2 = __float2bfloat16(f.z);
    __nv_bfloat16 h3 = __float2bfloat16(f.w);
    __nv_bfloat16 l0 = __float2bfloat16(f.x - __bfloat162float(h0));
    __nv_bfloat16 l1 = __float2bfloat16(f.y - __bfloat162float(h1));
    __nv_bfloat16 l2 = __float2bfloat16(f.z - __bfloat162float(h2));
    __nv_bfloat16 l3 = __float2bfloat16(f.w - __bfloat162float(h3));
    __nv_bfloat162 hp0(h0, h1), hp1(h2, h3), lp0(l0, l1), lp1(l2, l3);
    uint2 hv, lv;
    hv.x = *(uint32_t*)&hp0; hv.y = *(uint32_t*)&hp1;
    lv.x = *(uint32_t*)&lp0; lv.y = *(uint32_t*)&lp1;
    ((uint2*)hi)[i] = hv;
    ((uint2*)lo)[i] = lv;
}

// ---------------------------------------------------------------------------
// mma.sync GEMM: C[m,n] = sum_k A[m,k]*W[n,k], bf16x3 split, fp32 out.
// 128x256 CTA tile, 8 warps (32x128 each), K-chunk 32, 3-stage cp.async.
// Up to 3 (W,C) pairs selected by blockIdx.z (fused q/v/g projections).
// ---------------------------------------------------------------------------
struct GemmArgs {
    const __nv_bfloat16* Ah;
    const __nv_bfloat16* Al;
    const __nv_bfloat16* Wh[3];
    const __nv_bfloat16* Wl[3];
    float* C[3];
};

__global__ __launch_bounds__(256, 1)
void gemm_mma(const GemmArgs args)
{
    extern __shared__ char smem[];
    const uint32_t sbase = smem_to_u32(smem);
    const int tid  = threadIdx.x;
    const int lane = tid & 31;
    const int wid  = tid >> 5;
    const int wm   = wid & 3;        // warp row  (4 x 32 = 128 M)
    const int wn   = wid >> 2;       // warp col  (2 x 128 = 256 N)
    const int bn   = blockIdx.x * NT;
    const int bm   = blockIdx.y * MT;
    const int z    = blockIdx.z;

    const __nv_bfloat16* __restrict__ Ah = args.Ah;
    const __nv_bfloat16* __restrict__ Al = args.Al;
    const __nv_bfloat16* __restrict__ Wh = args.Wh[z];
    const __nv_bfloat16* __restrict__ Wl = args.Wl[z];
    float* __restrict__ C = args.C[z];

    // cp.async mapping: thread -> (row = tid>>2 (+64 steps), ch = tid&3)
    const int row0 = tid >> 2;            // 0..63
    const int ch0  = tid & 3;

    auto load_stage = [&](int st, int kc) {
        const uint32_t sb = sbase + (uint32_t)st * STAGE_BYTES;
        const int k0 = kc * KT;
        // A: 128 rows (2 reps)
        #pragma unroll
        for (int rep = 0; rep < 2; rep++) {
            int row = row0 + rep * 64;
            uint32_t sw = SWZ(row, ch0);
            const __nv_bfloat16* pa = Ah + (size_t)(bm + row) * Dc + k0 + ch0 * 8;
            const __nv_bfloat16* pl = Al + (size_t)(bm + row) * Dc + k0 + ch0 * 8;
            CP16(sb + OFF_AH + sw, pa);
            CP16(sb + OFF_AL + sw, pl);
        }
        // W: 256 rows (4 reps)
        #pragma unroll
        for (int rep = 0; rep < 4; rep++) {
            int row = row0 + rep * 64;
            uint32_t sw = SWZ(row, ch0);
            const __nv_bfloat16* pw = Wh + (size_t)(bn + row) * Dc + k0 + ch0 * 8;
            const __nv_bfloat16* pq = Wl + (size_t)(bn + row) * Dc + k0 + ch0 * 8;
            CP16(sb + OFF_WH + sw, pw);
            CP16(sb + OFF_WL + sw, pq);
        }
        asm volatile("cp.async.commit_group;" ::: "memory");
    };

    float c[2][16][4];
    #pragma unroll
    for (int i = 0; i < 2; i++)
        #pragma unroll
        for (int j = 0; j < 16; j++)
            #pragma unroll
            for (int k = 0; k < 4; k++) c[i][j][k] = 0.0f;

    load_stage(0, 0);
    load_stage(1, 1);

    // Per-lane ldmatrix address components
    const int a_r  = lane & 15;          // A m16k16: row within 16
    const int a_kc = lane >> 4;          // 16B k-chunk select
    const int b_r  = ((lane >> 4) << 3) + (lane & 7);  // B n16k16
    const int b_kc = (lane >> 3) & 1;

    for (int kc = 0; kc < NKC; kc++) {
        const int st = kc % NSTAGE;
        asm volatile("cp.async.wait_group 1;" ::: "memory");
        __syncthreads();

        if (kc + 2 < NKC) load_stage((kc + 2) % NSTAGE, kc + 2);
        else asm volatile("cp.async.commit_group;" ::: "memory");

        const uint32_t sb = sbase + (uint32_t)st * STAGE_BYTES;

        #pragma unroll
        for (int ks = 0; ks < 2; ks++) {
            uint32_t ah[2][4], al[2][4];
            #pragma unroll
            for (int mi = 0; mi < 2; mi++) {
                int row = wm * 32 + mi * 16 + a_r;
                int kk  = ks * 2 + a_kc;
                uint32_t sw = SWZ(row, kk);
                ldsm_x4(ah[mi], sb + OFF_AH + sw);
                ldsm_x4(al[mi], sb + OFF_AL + sw);
            }
            // Process B in two halves of 4 n16-tiles to bound live registers
            #pragma unroll
            for (int half = 0; half < 2; half++) {
                uint32_t bh[4][4], bl[4][4];
                #pragma unroll
                for (int p = 0; p < 4; p++) {
                    int pr  = half * 4 + p;
                    int row = wn * 128 + pr * 16 + b_r;
                    int kk  = ks * 2 + b_kc;
                    uint32_t sw = SWZ(row, kk);
                    ldsm_x4(bh[p], sb + OFF_WH + sw);
                    ldsm_x4(bl[p], sb + OFF_WL + sw);
                }
                #pragma unroll
                for (int mi = 0; mi < 2; mi++) {
                    #pragma unroll
                    for (int p = 0; p < 4; p++) {
                        int ni = (half * 4 + p) * 2;
                        mma16816(c[mi][ni+0], ah[mi], bh[p][0], bh[p][1]);
                        mma16816(c[mi][ni+1], ah[mi], bh[p][2], bh[p][3]);
                        mma16816(c[mi][ni+0], ah[mi], bl[p][0], bl[p][1]);
                        mma16816(c[mi][ni+1], ah[mi], bl[p][2], bl[p][3]);
                        mma16816(c[mi][ni+0], al[mi], bh[p][0], bh[p][1]);
                        mma16816(c[mi][ni+1], al[mi], bh[p][2], bh[p][3]);
                    }
                }
            }
        }
    }

    // Epilogue
    const int er = lane >> 2;
    const int ec = (lane & 3) * 2;
    #pragma unroll
    for (int mi = 0; mi < 2; mi++) {
        #pragma unroll
        for (int ni = 0; ni < 16; ni++) {
            size_t r0g = (size_t)(bm + wm * 32 + mi * 16 + er);
            size_t cg  = (size_t)(bn + wn * 128 + ni * 8 + ec);
            float2* p0 = (float2*)(C + r0g * Dc + cg);
            float2* p1 = (float2*)(C + (r0g + 8) * Dc + cg);
            *p0 = make_float2(c[mi][ni][0], c[mi][ni][1]);
            *p1 = make_float2(c[mi][ni][2], c[mi][ni][3]);
        }
    }
}

// ---------------------------------------------------------------------------
// Retention scan
// ---------------------------------------------------------------------------
__device__ __forceinline__ float lam_of(const float* beta, int h)
{
    float lam = 1.0f - exp2f(-beta[h]);
    lam = fmaxf(lam, 1.17549435e-38f);
    lam = fminf(lam, 1.0f);
    return lam;
}

__global__ __launch_bounds__(64)
void scan_pass1(const float* __restrict__ v, const float* __restrict__ beta)
{
    int blk = blockIdx.x;
    int cc  = blk % NC;
    int bh  = blk / NC;
    int h   = bh % Hc;
    int b   = bh / Hc;
    int dh  = threadIdx.x;

    float lam = lam_of(beta, h);
    size_t off = ((size_t)(b*Lc + cc*CHUNK)) * Dc + h*Dhc + dh;

    float s = 0.0f;
    #pragma unroll 4
    for (int t = 0; t < CHUNK; t++) {
        s = fmaf(lam, s, v[off]);
        off += Dc;
    }
    g_chunkS[(size_t)(bh*NC + cc)*Dhc + dh] = s;
}

__global__ __launch_bounds__(256)
void scan_pass2(const float* __restrict__ beta)
{
    int idx = blockIdx.x * blockDim.x + threadIdx.x;
    int dh  = idx % Dhc;
    int bh  = idx / Dhc;
    int h   = bh % Hc;

    float lam = lam_of(beta, h);
    float lamP = lam;
    #pragma unroll
    for (int i = 0; i < 7; i++) lamP = lamP * lamP;   // lam^128

    float carry = 0.0f;
    for (int cc = 0; cc < NC; cc++) {
        size_t pos = (size_t)(bh*NC + cc)*Dhc + dh;
        g_carry[pos] = carry;
        carry = fmaf(lamP, carry, g_chunkS[pos]);
    }
}

__global__ __launch_bounds__(64)
void scan_pass3(const float* __restrict__ v, float* __restrict__ q,
                const float* __restrict__ beta)
{
    int blk = blockIdx.x;
    int cc  = blk % NC;
    int bh  = blk / NC;
    int h   = bh % Hc;
    int b   = bh / Hc;
    int dh  = threadIdx.x;

    float lam = lam_of(beta, h);
    size_t off = ((size_t)(b*Lc + cc*CHUNK)) * Dc + h*Dhc + dh;

    float s = g_carry[(size_t)(bh*NC + cc)*Dhc + dh];
    #pragma unroll 4
    for (int t = 0; t < CHUNK; t++) {
        s = fmaf(lam, s, v[off]);
        q[off] = q[off] * s;
        off += Dc;
    }
}

// ---------------------------------------------------------------------------
// Fused LayerNorm(ret) * SiLU(gate) -> (zh, zl) bf16 split
// ---------------------------------------------------------------------------
__global__ __launch_bounds__(256)
void ln_gate_kernel(const float* __restrict__ ret, const float* __restrict__ gate,
                    const float* __restrict__ gamma, const float* __restrict__ lbeta,
                    __nv_bfloat16* __restrict__ zh, __nv_bfloat16* __restrict__ zl)
{
    const size_t row = blockIdx.x;
    const int tid = threadIdx.x;

    const float4 r = ((const float4*)(ret  + row*Dc))[tid];
    const float4 g = ((const float4*)(gate + row*Dc))[tid];

    float s  = r.x + r.y + r.z + r.w;
    float ss = r.x*r.x + r.y*r.y + r.z*r.z + r.w*r.w;

    #pragma unroll
    for (int o = 16; o > 0; o >>= 1) {
        s  += __shfl_xor_sync(0xffffffffu, s,  o);
        ss += __shfl_xor_sync(0xffffffffu, ss, o);
    }
    __shared__ float shs[8], shq[8];
    if ((tid & 31) == 0) { shs[tid>>5] = s; shq[tid>>5] = ss; }
    __syncthreads();

    float tot = 0.0f, totq = 0.0f;
    #pragma unroll
    for (int i = 0; i < 8; i++) { tot += shs[i]; totq += shq[i]; }

    const float inv = 1.0f / (float)Dc;
    float mu   = tot * inv;
    float var  = totq * inv - mu * mu;
    float rstd = rsqrtf(var + 1e-5f);

    const float4 gm = ((const float4*)gamma)[tid];
    const float4 bt = ((const float4*)lbeta)[tid];

    float4 o;
    o.x = ((r.x - mu)*rstd*gm.x + bt.x) * (g.x / (1.0f + expf(-g.x)));
    o.y = ((r.y - mu)*rstd*gm.y + bt.y) * (g.y / (1.0f + expf(-g.y)));
    o.z = ((r.z - mu)*rstd*gm.z + bt.z) * (g.z / (1.0f + expf(-g.z)));
    o.w = ((r.w - mu)*rstd*gm.w + bt.w) * (g.w / (1.0f + expf(-g.w)));

    __nv_bfloat16 h0 = __float2bfloat16(o.x), h1 = __float2bfloat16(o.y);
    __nv_bfloat16 h2 = __float2bfloat16(o.z), h3 = __float2bfloat16(o.w);
    __nv_bfloat16 l0 = __float2bfloat16(o.x - __bfloat162float(h0));
    __nv_bfloat16 l1 = __float2bfloat16(o.y - __bfloat162float(h1));
    __nv_bfloat16 l2 = __float2bfloat16(o.z - __bfloat162float(h2));
    __nv_bfloat16 l3 = __float2bfloat16(o.w - __bfloat162float(h3));
    __nv_bfloat162 hp0(h0, h1), hp1(h2, h3), lp0(l0, l1), lp1(l2, l3);
    uint2 hv, lv;
    hv.x = *(uint32_t*)&hp0; hv.y = *(uint32_t*)&hp1;
    lv.x = *(uint32_t*)&lp0; lv.y = *(uint32_t*)&lp1;
    ((uint2*)(zh + row*Dc))[tid] = hv;
    ((uint2*)(zl + row*Dc))[tid] = lv;
}

// ---------------------------------------------------------------------------
// Launch
// ---------------------------------------------------------------------------
extern "C" void kernel_launch(void* const* d_in, const int* in_sizes, int n_in,
                              void* d_out, int out_size)
{
    const float* x      = (const float*)d_in[0];
    const float* Wq     = (const float*)d_in[1];
    const float* Wv     = (const float*)d_in[2];
    const float* Wo     = (const float*)d_in[3];
    const float* Wg     = (const float*)d_in[4];
    const float* beta   = (const float*)d_in[5];
    const float* gamma  = (const float*)d_in[6];
    const float* lbeta  = (const float*)d_in[7];
    float* out          = (float*)d_out;

    float *q, *v, *g;
    __nv_bfloat16 *xh, *xl, *zh, *zl, *wh, *wl;
    cudaGetSymbolAddress((void**)&q, g_q);
    cudaGetSymbolAddress((void**)&v, g_v);
    cudaGetSymbolAddress((void**)&g, g_g);
    cudaGetSymbolAddress((void**)&xh, g_xh);
    cudaGetSymbolAddress((void**)&xl, g_xl);
    cudaGetSymbolAddress((void**)&zh, g_zh);
    cudaGetSymbolAddress((void**)&zl, g_zl);
    cudaGetSymbolAddress((void**)&wh, g_wh);
    cudaGetSymbolAddress((void**)&wl, g_wl);

    cudaFuncSetAttribute(gemm_mma, cudaFuncAttributeMaxDynamicSharedMemorySize, GEMM_SMEM);

    // Splits: one fused launch (x + 4 weights), grid.y selects tensor
    SplitArgs sa;
    sa.src[0] = x;  sa.hi[0] = xh; sa.lo[0] = xl; sa.n4[0] = Mtot*Dc/4;
    sa.src[1] = Wq; sa.hi[1] = wh + 0*(size_t)Dc*Dc; sa.lo[1] = wl + 0*(size_t)Dc*Dc; sa.n4[1] = Dc*Dc/4;
    sa.src[2] = Wv; sa.hi[2] = wh + 1*(size_t)Dc*Dc; sa.lo[2] = wl + 1*(size_t)Dc*Dc; sa.n4[2] = Dc*Dc/4;
    sa.src[3] = Wg; sa.hi[3] = wh + 2*(size_t)Dc*Dc; sa.lo[3] = wl + 2*(size_t)Dc*Dc; sa.n4[3] = Dc*Dc/4;
    sa.src[4] = Wo; sa.hi[4] = wh + 3*(size_t)Dc*Dc; sa.lo[4] = wl + 3*(size_t)Dc*Dc; sa.n4[4] = Dc*Dc/4;
    dim3 sgrid((Mtot*Dc/4 + 255)/256, 5);
    split_kernel<<<sgrid, 256>>>(sa);

    // Fused q/v/g projection GEMMs (z-indexed)
    GemmArgs a1;
    a1.Ah = xh; a1.Al = xl;
    a1.Wh[0] = wh + 0*(size_t)Dc*Dc; a1.Wl[0] = wl + 0*(size_t)Dc*Dc; a1.C[0] = q;
    a1.Wh[1] = wh + 1*(size_t)Dc*Dc; a1.Wl[1] = wl + 1*(size_t)Dc*Dc; a1.C[1] = v;
    a1.Wh[2] = wh + 2*(size_t)Dc*Dc; a1.Wl[2] = wl + 2*(size_t)Dc*Dc; a1.C[2] = g;
    dim3 grid_qvg(Dc/NT, Mtot/MT, 3);   // (4, 128, 3)
    gemm_mma<<<grid_qvg, 256, GEMM_SMEM>>>(a1);

    scan_pass1<<<Bc*Hc*NC, 64>>>(v, beta);
    scan_pass2<<<(Bc*Hc*Dhc)/256, 256>>>(beta);
    scan_pass3<<<Bc*Hc*NC, 64>>>(v, q, beta);   // q now holds ret

    ln_gate_kernel<<<Mtot, 256>>>(q, g, gamma, lbeta, zh, zl);

    // Output GEMM
    GemmArgs a2;
    a2.Ah = zh; a2.Al = zl;
    a2.Wh[0] = wh + 3*(size_t)Dc*Dc; a2.Wl[0] = wl + 3*(size_t)Dc*Dc; a2.C[0] = out;
    a2.Wh[1] = a2.Wh[0]; a2.Wl[1] = a2.Wl[0]; a2.C[1] = out;
    a2.Wh[2] = a2.Wh[0]; a2.Wl[2] = a2.Wl[0]; a2.C[2] = out;
    dim3 grid_o(Dc/NT, Mtot/MT, 1);     // (4, 128, 1)
    gemm_mma<<<grid_o, 256, GEMM_SMEM>>>(a2);
}

// round 6
// speedup vs baseline: 2.6275x; 1.0063x over previous
#include <cuda_runtime.h>
#include <cuda_bf16.h>
#include <math.h>
#include <stdint.h>

// Problem constants
#define Bc   4
#define Lc   4096
#define Dc   1024
#define Hc   16
#define Dhc  64
#define Mtot (Bc*Lc)        // 16384 rows
#define NC   32             // scan chunks per sequence
#define CHUNK (Lc/NC)       // 128

// GEMM tiling (mma.sync path)
#define MT 128
#define NT 256
#define KT 32               // k per stage
#define NKC (Dc/KT)         // 32 k-chunks
#define A_TILE (MT*KT*2)            // 8192
#define W_TILE (NT*KT*2)            // 16384
#define OFF_AH 0
#define OFF_AL (A_TILE)
#define OFF_WH (2*A_TILE)
#define OFF_WL (2*A_TILE + W_TILE)
#define STAGE_BYTES (2*A_TILE + 2*W_TILE)  // 49152
#define NSTAGE 4
#define GEMM_SMEM (NSTAGE*STAGE_BYTES)     // 196608

// Conflict-free swizzle: 16B-chunk c (0..3) xored with (row>>1)&3.
#define SWZ(row, ch) ((uint32_t)(row) * 64 + (uint32_t)((((ch) ^ (((row) >> 1) & 3)) & 3) * 16))

// ---------------------------------------------------------------------------
// Scratch (__device__ globals per allocation-free rule)
// ---------------------------------------------------------------------------
__device__ float g_q[Mtot*Dc];                 // q -> ret
__device__ float g_v[Mtot*Dc];                 // v
__device__ float g_g[Mtot*Dc];                 // gate pre-activation
__device__ float g_chunkS[Bc*Hc*NC*Dhc];
__device__ float g_carry [Bc*Hc*NC*Dhc];
__device__ __nv_bfloat16 g_xh[Mtot*Dc];
__device__ __nv_bfloat16 g_xl[Mtot*Dc];
__device__ __nv_bfloat16 g_zh[Mtot*Dc];
__device__ __nv_bfloat16 g_zl[Mtot*Dc];
__device__ __nv_bfloat16 g_wh[4*Dc*Dc];        // Wq,Wv,Wg,Wo hi
__device__ __nv_bfloat16 g_wl[4*Dc*Dc];        // lo

// ---------------------------------------------------------------------------
// PTX helpers (base ISA only: cp.async, ldmatrix, mma.sync)
// ---------------------------------------------------------------------------
__device__ __forceinline__ uint32_t smem_to_u32(const void* p) {
    uint32_t a;
    asm("{ .reg .u64 t; cvta.to.shared.u64 t, %1; cvt.u32.u64 %0, t; }" : "=r"(a) : "l"(p));
    return a;
}

#define CP16(dst, src) \
    asm volatile("cp.async.cg.shared.global [%0], [%1], 16;" :: "r"(dst), "l"(src) : "memory")

__device__ __forceinline__ void ldsm_x4(uint32_t (&r)[4], uint32_t addr) {
    asm volatile("ldmatrix.sync.aligned.m8n8.x4.shared.b16 {%0,%1,%2,%3}, [%4];"
        : "=r"(r[0]), "=r"(r[1]), "=r"(r[2]), "=r"(r[3]) : "r"(addr));
}

__device__ __forceinline__ void mma16816(float (&c)[4], const uint32_t (&a)[4],
                                         uint32_t b0, uint32_t b1) {
    asm volatile("mma.sync.aligned.m16n8k16.row.col.f32.bf16.bf16.f32 "
        "{%0,%1,%2,%3}, {%4,%5,%6,%7}, {%8,%9}, {%0,%1,%2,%3};"
        : "+f"(c[0]), "+f"(c[1]), "+f"(c[2]), "+f"(c[3])
        : "r"(a[0]), "r"(a[1]), "r"(a[2]), "r"(a[3]), "r"(b0), "r"(b1));
}

// ---------------------------------------------------------------------------
// Split fp32 -> (hi bf16, lo bf16); batched over up to 5 tensors via blockIdx.y
// ---------------------------------------------------------------------------
struct SplitArgs {
    const float* src[5];
    __nv_bfloat16* hi[5];
    __nv_bfloat16* lo[5];
    int n4[5];
};

__global__ __launch_bounds__(256)
void split_kernel(const SplitArgs args)
{
    const int z = blockIdx.y;
    const float* s = args.src[z];
    __nv_bfloat16* hi = args.hi[z];
    __nv_bfloat16* lo = args.lo[z];
    const int n4 = args.n4[z];

    int i = blockIdx.x * 256 + threadIdx.x;
    if (i >= n4) return;
    float4 f = ((const float4*)s)[i];
    __nv_bfloat16 h0 = __float2bfloat16(f.x);
    __nv_bfloat16 h1 = __float2bfloat16(f.y);
    __nv_bfloat16 h2 = __float2bfloat16(f.z);
    __nv_bfloat16 h3 = __float2bfloat16(f.w);
    __nv_bfloat16 l0 = __float2bfloat16(f.x - __bfloat162float(h0));
    __nv_bfloat16 l1 = __float2bfloat16(f.y - __bfloat162float(h1));
    __nv_bfloat16 l2 = __float2bfloat16(f.z - __bfloat162float(h2));
    __nv_bfloat16 l3 = __float2bfloat16(f.w - __bfloat162float(h3));
    __nv_bfloat162 hp0(h0, h1), hp1(h2, h3), lp0(l0, l1), lp1(l2, l3);
    uint2 hv, lv;
    hv.x = *(uint32_t*)&hp0; hv.y = *(uint32_t*)&hp1;
    lv.x = *(uint32_t*)&lp0; lv.y = *(uint32_t*)&lp1;
    ((uint2*)hi)[i] = hv;
    ((uint2*)lo)[i] = lv;
}

// ---------------------------------------------------------------------------
// mma.sync GEMM: C[m,n] = sum_k A[m,k]*W[n,k], bf16x3 split, fp32 out.
// 128x256 CTA tile, 8 warps (32x128 each), K-chunk 32, 4-stage cp.async.
// MMA terms issued hh-block, hl-block, lh-block to maximize accumulator
// reuse distance (16 MMAs) and keep the HMMA pipe free of RAW stalls.
// ---------------------------------------------------------------------------
struct GemmArgs {
    const __nv_bfloat16* Ah;
    const __nv_bfloat16* Al;
    const __nv_bfloat16* Wh[3];
    const __nv_bfloat16* Wl[3];
    float* C[3];
};

__global__ __launch_bounds__(256, 1)
void gemm_mma(const GemmArgs args)
{
    extern __shared__ char smem[];
    const uint32_t sbase = smem_to_u32(smem);
    const int tid  = threadIdx.x;
    const int lane = tid & 31;
    const int wid  = tid >> 5;
    const int wm   = wid & 3;        // warp row  (4 x 32 = 128 M)
    const int wn   = wid >> 2;       // warp col  (2 x 128 = 256 N)
    const int bn   = blockIdx.x * NT;
    const int bm   = blockIdx.y * MT;
    const int z    = blockIdx.z;

    const __nv_bfloat16* __restrict__ Ah = args.Ah;
    const __nv_bfloat16* __restrict__ Al = args.Al;
    const __nv_bfloat16* __restrict__ Wh = args.Wh[z];
    const __nv_bfloat16* __restrict__ Wl = args.Wl[z];
    float* __restrict__ C = args.C[z];

    const int row0 = tid >> 2;            // 0..63
    const int ch0  = tid & 3;

    auto load_stage = [&](int st, int kc) {
        const uint32_t sb = sbase + (uint32_t)st * STAGE_BYTES;
        const int k0 = kc * KT;
        #pragma unroll
        for (int rep = 0; rep < 2; rep++) {
            int row = row0 + rep * 64;
            uint32_t sw = SWZ(row, ch0);
            const __nv_bfloat16* pa = Ah + (size_t)(bm + row) * Dc + k0 + ch0 * 8;
            const __nv_bfloat16* pl = Al + (size_t)(bm + row) * Dc + k0 + ch0 * 8;
            CP16(sb + OFF_AH + sw, pa);
            CP16(sb + OFF_AL + sw, pl);
        }
        #pragma unroll
        for (int rep = 0; rep < 4; rep++) {
            int row = row0 + rep * 64;
            uint32_t sw = SWZ(row, ch0);
            const __nv_bfloat16* pw = Wh + (size_t)(bn + row) * Dc + k0 + ch0 * 8;
            const __nv_bfloat16* pq = Wl + (size_t)(bn + row) * Dc + k0 + ch0 * 8;
            CP16(sb + OFF_WH + sw, pw);
            CP16(sb + OFF_WL + sw, pq);
        }
        asm volatile("cp.async.commit_group;" ::: "memory");
    };

    float c[2][16][4];
    #pragma unroll
    for (int i = 0; i < 2; i++)
        #pragma unroll
        for (int j = 0; j < 16; j++)
            #pragma unroll
            for (int k = 0; k < 4; k++) c[i][j][k] = 0.0f;

    load_stage(0, 0);
    load_stage(1, 1);
    load_stage(2, 2);

    const int a_r  = lane & 15;
    const int a_kc = lane >> 4;
    const int b_r  = ((lane >> 4) << 3) + (lane & 7);
    const int b_kc = (lane >> 3) & 1;

    for (int kc = 0; kc < NKC; kc++) {
        const int st = kc % NSTAGE;
        asm volatile("cp.async.wait_group 2;" ::: "memory");
        __syncthreads();

        if (kc + 3 < NKC) load_stage((kc + 3) % NSTAGE, kc + 3);
        else asm volatile("cp.async.commit_group;" ::: "memory");

        const uint32_t sb = sbase + (uint32_t)st * STAGE_BYTES;

        #pragma unroll
        for (int ks = 0; ks < 2; ks++) {
            uint32_t ah[2][4], al[2][4];
            #pragma unroll
            for (int mi = 0; mi < 2; mi++) {
                int row = wm * 32 + mi * 16 + a_r;
                int kk  = ks * 2 + a_kc;
                uint32_t sw = SWZ(row, kk);
                ldsm_x4(ah[mi], sb + OFF_AH + sw);
                ldsm_x4(al[mi], sb + OFF_AL + sw);
            }
            #pragma unroll
            for (int half = 0; half < 2; half++) {
                uint32_t bh[4][4], bl[4][4];
                #pragma unroll
                for (int p = 0; p < 4; p++) {
                    int pr  = half * 4 + p;
                    int row = wn * 128 + pr * 16 + b_r;
                    int kk  = ks * 2 + b_kc;
                    uint32_t sw = SWZ(row, kk);
                    ldsm_x4(bh[p], sb + OFF_WH + sw);
                    ldsm_x4(bl[p], sb + OFF_WL + sw);
                }
                // Term 1: Ah x Wh  (16 MMAs, all-distinct accumulators)
                #pragma unroll
                for (int mi = 0; mi < 2; mi++)
                    #pragma unroll
                    for (int p = 0; p < 4; p++) {
                        int ni = (half * 4 + p) * 2;
                        mma16816(c[mi][ni+0], ah[mi], bh[p][0], bh[p][1]);
                        mma16816(c[mi][ni+1], ah[mi], bh[p][2], bh[p][3]);
                    }
                // Term 2: Ah x Wl
                #pragma unroll
                for (int mi = 0; mi < 2; mi++)
                    #pragma unroll
                    for (int p = 0; p < 4; p++) {
                        int ni = (half * 4 + p) * 2;
                        mma16816(c[mi][ni+0], ah[mi], bl[p][0], bl[p][1]);
                        mma16816(c[mi][ni+1], ah[mi], bl[p][2], bl[p][3]);
                    }
                // Term 3: Al x Wh
                #pragma unroll
                for (int mi = 0; mi < 2; mi++)
                    #pragma unroll
                    for (int p = 0; p < 4; p++) {
                        int ni = (half * 4 + p) * 2;
                        mma16816(c[mi][ni+0], al[mi], bh[p][0], bh[p][1]);
                        mma16816(c[mi][ni+1], al[mi], bh[p][2], bh[p][3]);
                    }
            }
        }
    }

    // Epilogue
    const int er = lane >> 2;
    const int ec = (lane & 3) * 2;
    #pragma unroll
    for (int mi = 0; mi < 2; mi++) {
        #pragma unroll
        for (int ni = 0; ni < 16; ni++) {
            size_t r0g = (size_t)(bm + wm * 32 + mi * 16 + er);
            size_t cg  = (size_t)(bn + wn * 128 + ni * 8 + ec);
            float2* p0 = (float2*)(C + r0g * Dc + cg);
            float2* p1 = (float2*)(C + (r0g + 8) * Dc + cg);
            *p0 = make_float2(c[mi][ni][0], c[mi][ni][1]);
            *p1 = make_float2(c[mi][ni][2], c[mi][ni][3]);
        }
    }
}

// ---------------------------------------------------------------------------
// Retention scan
// ---------------------------------------------------------------------------
__device__ __forceinline__ float lam_of(const float* beta, int h)
{
    float lam = 1.0f - exp2f(-beta[h]);
    lam = fmaxf(lam, 1.17549435e-38f);
    lam = fminf(lam, 1.0f);
    return lam;
}

__global__ __launch_bounds__(64)
void scan_pass1(const float* __restrict__ v, const float* __restrict__ beta)
{
    int blk = blockIdx.x;
    int cc  = blk % NC;
    int bh  = blk / NC;
    int h   = bh % Hc;
    int b   = bh / Hc;
    int dh  = threadIdx.x;

    float lam = lam_of(beta, h);
    size_t off = ((size_t)(b*Lc + cc*CHUNK)) * Dc + h*Dhc + dh;

    float s = 0.0f;
    #pragma unroll 4
    for (int t = 0; t < CHUNK; t++) {
        s = fmaf(lam, s, v[off]);
        off += Dc;
    }
    g_chunkS[(size_t)(bh*NC + cc)*Dhc + dh] = s;
}

__global__ __launch_bounds__(256)
void scan_pass2(const float* __restrict__ beta)
{
    int idx = blockIdx.x * blockDim.x + threadIdx.x;
    int dh  = idx % Dhc;
    int bh  = idx / Dhc;
    int h   = bh % Hc;

    float lam = lam_of(beta, h);
    float lamP = lam;
    #pragma unroll
    for (int i = 0; i < 7; i++) lamP = lamP * lamP;   // lam^128

    float carry = 0.0f;
    for (int cc = 0; cc < NC; cc++) {
        size_t pos = (size_t)(bh*NC + cc)*Dhc + dh;
        g_carry[pos] = carry;
        carry = fmaf(lamP, carry, g_chunkS[pos]);
    }
}

__global__ __launch_bounds__(64)
void scan_pass3(const float* __restrict__ v, float* __restrict__ q,
                const float* __restrict__ beta)
{
    int blk = blockIdx.x;
    int cc  = blk % NC;
    int bh  = blk / NC;
    int h   = bh % Hc;
    int b   = bh / Hc;
    int dh  = threadIdx.x;

    float lam = lam_of(beta, h);
    size_t off = ((size_t)(b*Lc + cc*CHUNK)) * Dc + h*Dhc + dh;

    float s = g_carry[(size_t)(bh*NC + cc)*Dhc + dh];
    #pragma unroll 4
    for (int t = 0; t < CHUNK; t++) {
        s = fmaf(lam, s, v[off]);
        q[off] = q[off] * s;
        off += Dc;
    }
}

// ---------------------------------------------------------------------------
// Fused LayerNorm(ret) * SiLU(gate) -> (zh, zl) bf16 split
// ---------------------------------------------------------------------------
__global__ __launch_bounds__(256)
void ln_gate_kernel(const float* __restrict__ ret, const float* __restrict__ gate,
                    const float* __restrict__ gamma, const float* __restrict__ lbeta,
                    __nv_bfloat16* __restrict__ zh, __nv_bfloat16* __restrict__ zl)
{
    const size_t row = blockIdx.x;
    const int tid = threadIdx.x;

    const float4 r = ((const float4*)(ret  + row*Dc))[tid];
    const float4 g = ((const float4*)(gate + row*Dc))[tid];

    float s  = r.x + r.y + r.z + r.w;
    float ss = r.x*r.x + r.y*r.y + r.z*r.z + r.w*r.w;

    #pragma unroll
    for (int o = 16; o > 0; o >>= 1) {
        s  += __shfl_xor_sync(0xffffffffu, s,  o);
        ss += __shfl_xor_sync(0xffffffffu, ss, o);
    }
    __shared__ float shs[8], shq[8];
    if ((tid & 31) == 0) { shs[tid>>5] = s; shq[tid>>5] = ss; }
    __syncthreads();

    float tot = 0.0f, totq = 0.0f;
    #pragma unroll
    for (int i = 0; i < 8; i++) { tot += shs[i]; totq += shq[i]; }

    const float inv = 1.0f / (float)Dc;
    float mu   = tot * inv;
    float var  = totq * inv - mu * mu;
    float rstd = rsqrtf(var + 1e-5f);

    const float4 gm = ((const float4*)gamma)[tid];
    const float4 bt = ((const float4*)lbeta)[tid];

    float4 o;
    o.x = ((r.x - mu)*rstd*gm.x + bt.x) * (g.x / (1.0f + expf(-g.x)));
    o.y = ((r.y - mu)*rstd*gm.y + bt.y) * (g.y / (1.0f + expf(-g.y)));
    o.z = ((r.z - mu)*rstd*gm.z + bt.z) * (g.z / (1.0f + expf(-g.z)));
    o.w = ((r.w - mu)*rstd*gm.w + bt.w) * (g.w / (1.0f + expf(-g.w)));

    __nv_bfloat16 h0 = __float2bfloat16(o.x), h1 = __float2bfloat16(o.y);
    __nv_bfloat16 h2 = __float2bfloat16(o.z), h3 = __float2bfloat16(o.w);
    __nv_bfloat16 l0 = __float2bfloat16(o.x - __bfloat162float(h0));
    __nv_bfloat16 l1 = __float2bfloat16(o.y - __bfloat162float(h1));
    __nv_bfloat16 l2 = __float2bfloat16(o.z - __bfloat162float(h2));
    __nv_bfloat16 l3 = __float2bfloat16(o.w - __bfloat162float(h3));
    __nv_bfloat162 hp0(h0, h1), hp1(h2, h3), lp0(l0, l1), lp1(l2, l3);
    uint2 hv, lv;
    hv.x = *(uint32_t*)&hp0; hv.y = *(uint32_t*)&hp1;
    lv.x = *(uint32_t*)&lp0; lv.y = *(uint32_t*)&lp1;
    ((uint2*)(zh + row*Dc))[tid] = hv;
    ((uint2*)(zl + row*Dc))[tid] = lv;
}

// ---------------------------------------------------------------------------
// Launch
// ---------------------------------------------------------------------------
extern "C" void kernel_launch(void* const* d_in, const int* in_sizes, int n_in,
                              void* d_out, int out_size)
{
    const float* x      = (const float*)d_in[0];
    const float* Wq     = (const float*)d_in[1];
    const float* Wv     = (const float*)d_in[2];
    const float* Wo     = (const float*)d_in[3];
    const float* Wg     = (const float*)d_in[4];
    const float* beta   = (const float*)d_in[5];
    const float* gamma  = (const float*)d_in[6];
    const float* lbeta  = (const float*)d_in[7];
    float* out          = (float*)d_out;

    float *q, *v, *g;
    __nv_bfloat16 *xh, *xl, *zh, *zl, *wh, *wl;
    cudaGetSymbolAddress((void**)&q, g_q);
    cudaGetSymbolAddress((void**)&v, g_v);
    cudaGetSymbolAddress((void**)&g, g_g);
    cudaGetSymbolAddress((void**)&xh, g_xh);
    cudaGetSymbolAddress((void**)&xl, g_xl);
    cudaGetSymbolAddress((void**)&zh, g_zh);
    cudaGetSymbolAddress((void**)&zl, g_zl);
    cudaGetSymbolAddress((void**)&wh, g_wh);
    cudaGetSymbolAddress((void**)&wl, g_wl);

    cudaFuncSetAttribute(gemm_mma, cudaFuncAttributeMaxDynamicSharedMemorySize, GEMM_SMEM);

    // Splits: one fused launch (x + 4 weights), grid.y selects tensor
    SplitArgs sa;
    sa.src[0] = x;  sa.hi[0] = xh; sa.lo[0] = xl; sa.n4[0] = Mtot*Dc/4;
    sa.src[1] = Wq; sa.hi[1] = wh + 0*(size_t)Dc*Dc; sa.lo[1] = wl + 0*(size_t)Dc*Dc; sa.n4[1] = Dc*Dc/4;
    sa.src[2] = Wv; sa.hi[2] = wh + 1*(size_t)Dc*Dc; sa.lo[2] = wl + 1*(size_t)Dc*Dc; sa.n4[2] = Dc*Dc/4;
    sa.src[3] = Wg; sa.hi[3] = wh + 2*(size_t)Dc*Dc; sa.lo[3] = wl + 2*(size_t)Dc*Dc; sa.n4[3] = Dc*Dc/4;
    sa.src[4] = Wo; sa.hi[4] = wh + 3*(size_t)Dc*Dc; sa.lo[4] = wl + 3*(size_t)Dc*Dc; sa.n4[4] = Dc*Dc/4;
    dim3 sgrid((Mtot*Dc/4 + 255)/256, 5);
    split_kernel<<<sgrid, 256>>>(sa);

    // Fused q/v/g projection GEMMs (z-indexed)
    GemmArgs a1;
    a1.Ah = xh; a1.Al = xl;
    a1.Wh[0] = wh + 0*(size_t)Dc*Dc; a1.Wl[0] = wl + 0*(size_t)Dc*Dc; a1.C[0] = q;
    a1.Wh[1] = wh + 1*(size_t)Dc*Dc; a1.Wl[1] = wl + 1*(size_t)Dc*Dc; a1.C[1] = v;
    a1.Wh[2] = wh + 2*(size_t)Dc*Dc; a1.Wl[2] = wl + 2*(size_t)Dc*Dc; a1.C[2] = g;
    dim3 grid_qvg(Dc/NT, Mtot/MT, 3);   // (4, 128, 3)
    gemm_mma<<<grid_qvg, 256, GEMM_SMEM>>>(a1);

    scan_pass1<<<Bc*Hc*NC, 64>>>(v, beta);
    scan_pass2<<<(Bc*Hc*Dhc)/256, 256>>>(beta);
    scan_pass3<<<Bc*Hc*NC, 64>>>(v, q, beta);   // q now holds ret

    ln_gate_kernel<<<Mtot, 256>>>(q, g, gamma, lbeta, zh, zl);

    // Output GEMM
    GemmArgs a2;
    a2.Ah = zh; a2.Al = zl;
    a2.Wh[0] = wh + 3*(size_t)Dc*Dc; a2.Wl[0] = wl + 3*(size_t)Dc*Dc; a2.C[0] = out;
    a2.Wh[1] = a2.Wh[0]; a2.Wl[1] = a2.Wl[0]; a2.C[1] = out;
    a2.Wh[2] = a2.Wh[0]; a2.Wl[2] = a2.Wl[0]; a2.C[2] = out;
    dim3 grid_o(Dc/NT, Mtot/MT, 1);     // (4, 128, 1)
    gemm_mma<<<grid_o, 256, GEMM_SMEM>>>(a2);
}

// round 7
// speedup vs baseline: 2.9950x; 1.1399x over previous
#include <cuda_runtime.h>
#include <cuda_bf16.h>
#include <math.h>
#include <stdint.h>

// Problem constants
#define Bc   4
#define Lc   4096
#define Dc   1024
#define Hc   16
#define Dhc  64
#define Mtot (Bc*Lc)        // 16384 rows
#define NC   32             // scan chunks per sequence
#define CHUNK (Lc/NC)       // 128

// GEMM tiling (mma.sync path): 128x128 tile, 2 CTAs/SM
#define MT 128
#define NT 128
#define KT 32               // k per stage
#define NKC (Dc/KT)         // 32 k-chunks
#define A_TILE (MT*KT*2)            // 8192
#define W_TILE (NT*KT*2)            // 8192
#define OFF_AH 0
#define OFF_AL (A_TILE)
#define OFF_WH (2*A_TILE)
#define OFF_WL (3*A_TILE)
#define STAGE_BYTES (4*A_TILE)      // 32768
#define NSTAGE 3
#define GEMM_SMEM (NSTAGE*STAGE_BYTES)     // 98304

// Conflict-free swizzle: 16B-chunk c (0..3) xored with (row>>1)&3.
#define SWZ(row, ch) ((uint32_t)(row) * 64 + (uint32_t)((((ch) ^ (((row) >> 1) & 3)) & 3) * 16))

// ---------------------------------------------------------------------------
// Scratch (__device__ globals per allocation-free rule)
// ---------------------------------------------------------------------------
__device__ float g_q[Mtot*Dc];                 // q -> ret
__device__ float g_v[Mtot*Dc];                 // v
__device__ float g_g[Mtot*Dc];                 // gate pre-activation
__device__ float g_chunkS[Bc*Hc*NC*Dhc];
__device__ float g_carry [Bc*Hc*NC*Dhc];
__device__ __nv_bfloat16 g_xh[Mtot*Dc];
__device__ __nv_bfloat16 g_xl[Mtot*Dc];
__device__ __nv_bfloat16 g_zh[Mtot*Dc];
__device__ __nv_bfloat16 g_zl[Mtot*Dc];
__device__ __nv_bfloat16 g_wh[4*Dc*Dc];        // Wq,Wv,Wg,Wo hi
__device__ __nv_bfloat16 g_wl[4*Dc*Dc];        // lo

// ---------------------------------------------------------------------------
// PTX helpers (base ISA only: cp.async, ldmatrix, mma.sync)
// ---------------------------------------------------------------------------
__device__ __forceinline__ uint32_t smem_to_u32(const void* p) {
    uint32_t a;
    asm("{ .reg .u64 t; cvta.to.shared.u64 t, %1; cvt.u32.u64 %0, t; }" : "=r"(a) : "l"(p));
    return a;
}

#define CP16(dst, src) \
    asm volatile("cp.async.cg.shared.global [%0], [%1], 16;" :: "r"(dst), "l"(src) : "memory")

__device__ __forceinline__ void ldsm_x4(uint32_t (&r)[4], uint32_t addr) {
    asm volatile("ldmatrix.sync.aligned.m8n8.x4.shared.b16 {%0,%1,%2,%3}, [%4];"
        : "=r"(r[0]), "=r"(r[1]), "=r"(r[2]), "=r"(r[3]) : "r"(addr));
}

__device__ __forceinline__ void mma16816(float (&c)[4], const uint32_t (&a)[4],
                                         uint32_t b0, uint32_t b1) {
    asm volatile("mma.sync.aligned.m16n8k16.row.col.f32.bf16.bf16.f32 "
        "{%0,%1,%2,%3}, {%4,%5,%6,%7}, {%8,%9}, {%0,%1,%2,%3};"
        : "+f"(c[0]), "+f"(c[1]), "+f"(c[2]), "+f"(c[3])
        : "r"(a[0]), "r"(a[1]), "r"(a[2]), "r"(a[3]), "r"(b0), "r"(b1));
}

// ---------------------------------------------------------------------------
// Split fp32 -> (hi bf16, lo bf16); batched over up to 5 tensors via blockIdx.y
// ---------------------------------------------------------------------------
struct SplitArgs {
    const float* src[5];
    __nv_bfloat16* hi[5];
    __nv_bfloat16* lo[5];
    int n4[5];
};

__global__ __launch_bounds__(256)
void split_kernel(const SplitArgs args)
{
    const int z = blockIdx.y;
    const float* s = args.src[z];
    __nv_bfloat16* hi = args.hi[z];
    __nv_bfloat16* lo = args.lo[z];
    const int n4 = args.n4[z];

    int i = blockIdx.x * 256 + threadIdx.x;
    if (i >= n4) return;
    float4 f = ((const float4*)s)[i];
    __nv_bfloat16 h0 = __float2bfloat16(f.x);
    __nv_bfloat16 h1 = __float2bfloat16(f.y);
    __nv_bfloat16 h2 = __float2bfloat16(f.z);
    __nv_bfloat16 h3 = __float2bfloat16(f.w);
    __nv_bfloat16 l0 = __float2bfloat16(f.x - __bfloat162float(h0));
    __nv_bfloat16 l1 = __float2bfloat16(f.y - __bfloat162float(h1));
    __nv_bfloat16 l2 = __float2bfloat16(f.z - __bfloat162float(h2));
    __nv_bfloat16 l3 = __float2bfloat16(f.w - __bfloat162float(h3));
    __nv_bfloat162 hp0(h0, h1), hp1(h2, h3), lp0(l0, l1), lp1(l2, l3);
    uint2 hv, lv;
    hv.x = *(uint32_t*)&hp0; hv.y = *(uint32_t*)&hp1;
    lv.x = *(uint32_t*)&lp0; lv.y = *(uint32_t*)&lp1;
    ((uint2*)hi)[i] = hv;
    ((uint2*)lo)[i] = lv;
}

// ---------------------------------------------------------------------------
// mma.sync GEMM: C[m,n] = sum_k A[m,k]*W[n,k], bf16x3 split, fp32 out.
// 128x128 CTA tile, 8 warps (32x64 each), K-chunk 32, 3-stage cp.async,
// 2 CTAs/SM for latency hiding (4 warps/SMSP).
// ---------------------------------------------------------------------------
struct GemmArgs {
    const __nv_bfloat16* Ah;
    const __nv_bfloat16* Al;
    const __nv_bfloat16* Wh[3];
    const __nv_bfloat16* Wl[3];
    float* C[3];
};

__global__ __launch_bounds__(256, 2)
void gemm_mma(const GemmArgs args)
{
    extern __shared__ char smem[];
    const uint32_t sbase = smem_to_u32(smem);
    const int tid  = threadIdx.x;
    const int lane = tid & 31;
    const int wid  = tid >> 5;
    const int wm   = wid & 3;        // warp row  (4 x 32 = 128 M)
    const int wn   = wid >> 2;       // warp col  (2 x 64 = 128 N)
    const int bn   = blockIdx.x * NT;
    const int bm   = blockIdx.y * MT;
    const int z    = blockIdx.z;

    const __nv_bfloat16* __restrict__ Ah = args.Ah;
    const __nv_bfloat16* __restrict__ Al = args.Al;
    const __nv_bfloat16* __restrict__ Wh = args.Wh[z];
    const __nv_bfloat16* __restrict__ Wl = args.Wl[z];
    float* __restrict__ C = args.C[z];

    const int row0 = tid >> 2;            // 0..63
    const int ch0  = tid & 3;

    auto load_stage = [&](int st, int kc) {
        const uint32_t sb = sbase + (uint32_t)st * STAGE_BYTES;
        const int k0 = kc * KT;
        #pragma unroll
        for (int rep = 0; rep < 2; rep++) {
            int row = row0 + rep * 64;
            uint32_t sw = SWZ(row, ch0);
            const __nv_bfloat16* pa = Ah + (size_t)(bm + row) * Dc + k0 + ch0 * 8;
            const __nv_bfloat16* pl = Al + (size_t)(bm + row) * Dc + k0 + ch0 * 8;
            const __nv_bfloat16* pw = Wh + (size_t)(bn + row) * Dc + k0 + ch0 * 8;
            const __nv_bfloat16* pq = Wl + (size_t)(bn + row) * Dc + k0 + ch0 * 8;
            CP16(sb + OFF_AH + sw, pa);
            CP16(sb + OFF_AL + sw, pl);
            CP16(sb + OFF_WH + sw, pw);
            CP16(sb + OFF_WL + sw, pq);
        }
        asm volatile("cp.async.commit_group;" ::: "memory");
    };

    float c[2][8][4];
    #pragma unroll
    for (int i = 0; i < 2; i++)
        #pragma unroll
        for (int j = 0; j < 8; j++)
            #pragma unroll
            for (int k = 0; k < 4; k++) c[i][j][k] = 0.0f;

    load_stage(0, 0);
    load_stage(1, 1);

    const int a_r  = lane & 15;
    const int a_kc = lane >> 4;
    const int b_r  = ((lane >> 4) << 3) + (lane & 7);
    const int b_kc = (lane >> 3) & 1;

    for (int kc = 0; kc < NKC; kc++) {
        const int st = kc % NSTAGE;
        asm volatile("cp.async.wait_group 1;" ::: "memory");
        __syncthreads();

        if (kc + 2 < NKC) load_stage((kc + 2) % NSTAGE, kc + 2);
        else asm volatile("cp.async.commit_group;" ::: "memory");

        const uint32_t sb = sbase + (uint32_t)st * STAGE_BYTES;

        #pragma unroll
        for (int ks = 0; ks < 2; ks++) {
            uint32_t ah[2][4], al[2][4];
            #pragma unroll
            for (int mi = 0; mi < 2; mi++) {
                int row = wm * 32 + mi * 16 + a_r;
                int kk  = ks * 2 + a_kc;
                uint32_t sw = SWZ(row, kk);
                ldsm_x4(ah[mi], sb + OFF_AH + sw);
                ldsm_x4(al[mi], sb + OFF_AL + sw);
            }
            #pragma unroll
            for (int half = 0; half < 2; half++) {
                uint32_t bh[2][4], bl[2][4];
                #pragma unroll
                for (int p = 0; p < 2; p++) {
                    int pr  = half * 2 + p;
                    int row = wn * 64 + pr * 16 + b_r;
                    int kk  = ks * 2 + b_kc;
                    uint32_t sw = SWZ(row, kk);
                    ldsm_x4(bh[p], sb + OFF_WH + sw);
                    ldsm_x4(bl[p], sb + OFF_WL + sw);
                }
                // Term-blocked: hh (8 distinct accs), then hl, then lh
                #pragma unroll
                for (int mi = 0; mi < 2; mi++)
                    #pragma unroll
                    for (int p = 0; p < 2; p++) {
                        int ni = (half * 2 + p) * 2;
                        mma16816(c[mi][ni+0], ah[mi], bh[p][0], bh[p][1]);
                        mma16816(c[mi][ni+1], ah[mi], bh[p][2], bh[p][3]);
                    }
                #pragma unroll
                for (int mi = 0; mi < 2; mi++)
                    #pragma unroll
                    for (int p = 0; p < 2; p++) {
                        int ni = (half * 2 + p) * 2;
                        mma16816(c[mi][ni+0], ah[mi], bl[p][0], bl[p][1]);
                        mma16816(c[mi][ni+1], ah[mi], bl[p][2], bl[p][3]);
                    }
                #pragma unroll
                for (int mi = 0; mi < 2; mi++)
                    #pragma unroll
                    for (int p = 0; p < 2; p++) {
                        int ni = (half * 2 + p) * 2;
                        mma16816(c[mi][ni+0], al[mi], bh[p][0], bh[p][1]);
                        mma16816(c[mi][ni+1], al[mi], bh[p][2], bh[p][3]);
                    }
            }
        }
    }

    // Epilogue
    const int er = lane >> 2;
    const int ec = (lane & 3) * 2;
    #pragma unroll
    for (int mi = 0; mi < 2; mi++) {
        #pragma unroll
        for (int ni = 0; ni < 8; ni++) {
            size_t r0g = (size_t)(bm + wm * 32 + mi * 16 + er);
            size_t cg  = (size_t)(bn + wn * 64 + ni * 8 + ec);
            float2* p0 = (float2*)(C + r0g * Dc + cg);
            float2* p1 = (float2*)(C + (r0g + 8) * Dc + cg);
            *p0 = make_float2(c[mi][ni][0], c[mi][ni][1]);
            *p1 = make_float2(c[mi][ni][2], c[mi][ni][3]);
        }
    }
}

// ---------------------------------------------------------------------------
// Retention scan
// ---------------------------------------------------------------------------
__device__ __forceinline__ float lam_of(const float* beta, int h)
{
    float lam = 1.0f - exp2f(-beta[h]);
    lam = fmaxf(lam, 1.17549435e-38f);
    lam = fminf(lam, 1.0f);
    return lam;
}

__global__ __launch_bounds__(64)
void scan_pass1(const float* __restrict__ v, const float* __restrict__ beta)
{
    int blk = blockIdx.x;
    int cc  = blk % NC;
    int bh  = blk / NC;
    int h   = bh % Hc;
    int b   = bh / Hc;
    int dh  = threadIdx.x;

    float lam = lam_of(beta, h);
    size_t off = ((size_t)(b*Lc + cc*CHUNK)) * Dc + h*Dhc + dh;

    float s = 0.0f;
    #pragma unroll 4
    for (int t = 0; t < CHUNK; t++) {
        s = fmaf(lam, s, v[off]);
        off += Dc;
    }
    g_chunkS[(size_t)(bh*NC + cc)*Dhc + dh] = s;
}

__global__ __launch_bounds__(256)
void scan_pass2(const float* __restrict__ beta)
{
    int idx = blockIdx.x * blockDim.x + threadIdx.x;
    int dh  = idx % Dhc;
    int bh  = idx / Dhc;
    int h   = bh % Hc;

    float lam = lam_of(beta, h);
    float lamP = lam;
    #pragma unroll
    for (int i = 0; i < 7; i++) lamP = lamP * lamP;   // lam^128

    float carry = 0.0f;
    for (int cc = 0; cc < NC; cc++) {
        size_t pos = (size_t)(bh*NC + cc)*Dhc + dh;
        g_carry[pos] = carry;
        carry = fmaf(lamP, carry, g_chunkS[pos]);
    }
}

__global__ __launch_bounds__(64)
void scan_pass3(const float* __restrict__ v, float* __restrict__ q,
                const float* __restrict__ beta)
{
    int blk = blockIdx.x;
    int cc  = blk % NC;
    int bh  = blk / NC;
    int h   = bh % Hc;
    int b   = bh / Hc;
    int dh  = threadIdx.x;

    float lam = lam_of(beta, h);
    size_t off = ((size_t)(b*Lc + cc*CHUNK)) * Dc + h*Dhc + dh;

    float s = g_carry[(size_t)(bh*NC + cc)*Dhc + dh];
    #pragma unroll 4
    for (int t = 0; t < CHUNK; t++) {
        s = fmaf(lam, s, v[off]);
        q[off] = q[off] * s;
        off += Dc;
    }
}

// ---------------------------------------------------------------------------
// Fused LayerNorm(ret) * SiLU(gate) -> (zh, zl) bf16 split
// ---------------------------------------------------------------------------
__global__ __launch_bounds__(256)
void ln_gate_kernel(const float* __restrict__ ret, const float* __restrict__ gate,
                    const float* __restrict__ gamma, const float* __restrict__ lbeta,
                    __nv_bfloat16* __restrict__ zh, __nv_bfloat16* __restrict__ zl)
{
    const size_t row = blockIdx.x;
    const int tid = threadIdx.x;

    const float4 r = ((const float4*)(ret  + row*Dc))[tid];
    const float4 g = ((const float4*)(gate + row*Dc))[tid];

    float s  = r.x + r.y + r.z + r.w;
    float ss = r.x*r.x + r.y*r.y + r.z*r.z + r.w*r.w;

    #pragma unroll
    for (int o = 16; o > 0; o >>= 1) {
        s  += __shfl_xor_sync(0xffffffffu, s,  o);
        ss += __shfl_xor_sync(0xffffffffu, ss, o);
    }
    __shared__ float shs[8], shq[8];
    if ((tid & 31) == 0) { shs[tid>>5] = s; shq[tid>>5] = ss; }
    __syncthreads();

    float tot = 0.0f, totq = 0.0f;
    #pragma unroll
    for (int i = 0; i < 8; i++) { tot += shs[i]; totq += shq[i]; }

    const float inv = 1.0f / (float)Dc;
    float mu   = tot * inv;
    float var  = totq * inv - mu * mu;
    float rstd = rsqrtf(var + 1e-5f);

    const float4 gm = ((const float4*)gamma)[tid];
    const float4 bt = ((const float4*)lbeta)[tid];

    float4 o;
    o.x = ((r.x - mu)*rstd*gm.x + bt.x) * (g.x / (1.0f + expf(-g.x)));
    o.y = ((r.y - mu)*rstd*gm.y + bt.y) * (g.y / (1.0f + expf(-g.y)));
    o.z = ((r.z - mu)*rstd*gm.z + bt.z) * (g.z / (1.0f + expf(-g.z)));
    o.w = ((r.w - mu)*rstd*gm.w + bt.w) * (g.w / (1.0f + expf(-g.w)));

    __nv_bfloat16 h0 = __float2bfloat16(o.x), h1 = __float2bfloat16(o.y);
    __nv_bfloat16 h2 = __float2bfloat16(o.z), h3 = __float2bfloat16(o.w);
    __nv_bfloat16 l0 = __float2bfloat16(o.x - __bfloat162float(h0));
    __nv_bfloat16 l1 = __float2bfloat16(o.y - __bfloat162float(h1));
    __nv_bfloat16 l2 = __float2bfloat16(o.z - __bfloat162float(h2));
    __nv_bfloat16 l3 = __float2bfloat16(o.w - __bfloat162float(h3));
    __nv_bfloat162 hp0(h0, h1), hp1(h2, h3), lp0(l0, l1), lp1(l2, l3);
    uint2 hv, lv;
    hv.x = *(uint32_t*)&hp0; hv.y = *(uint32_t*)&hp1;
    lv.x = *(uint32_t*)&lp0; lv.y = *(uint32_t*)&lp1;
    ((uint2*)(zh + row*Dc))[tid] = hv;
    ((uint2*)(zl + row*Dc))[tid] = lv;
}

// ---------------------------------------------------------------------------
// Launch
// ---------------------------------------------------------------------------
extern "C" void kernel_launch(void* const* d_in, const int* in_sizes, int n_in,
                              void* d_out, int out_size)
{
    const float* x      = (const float*)d_in[0];
    const float* Wq     = (const float*)d_in[1];
    const float* Wv     = (const float*)d_in[2];
    const float* Wo     = (const float*)d_in[3];
    const float* Wg     = (const float*)d_in[4];
    const float* beta   = (const float*)d_in[5];
    const float* gamma  = (const float*)d_in[6];
    const float* lbeta  = (const float*)d_in[7];
    float* out          = (float*)d_out;

    float *q, *v, *g;
    __nv_bfloat16 *xh, *xl, *zh, *zl, *wh, *wl;
    cudaGetSymbolAddress((void**)&q, g_q);
    cudaGetSymbolAddress((void**)&v, g_v);
    cudaGetSymbolAddress((void**)&g, g_g);
    cudaGetSymbolAddress((void**)&xh, g_xh);
    cudaGetSymbolAddress((void**)&xl, g_xl);
    cudaGetSymbolAddress((void**)&zh, g_zh);
    cudaGetSymbolAddress((void**)&zl, g_zl);
    cudaGetSymbolAddress((void**)&wh, g_wh);
    cudaGetSymbolAddress((void**)&wl, g_wl);

    cudaFuncSetAttribute(gemm_mma, cudaFuncAttributeMaxDynamicSharedMemorySize, GEMM_SMEM);

    // Splits: one fused launch (x + 4 weights), grid.y selects tensor
    SplitArgs sa;
    sa.src[0] = x;  sa.hi[0] = xh; sa.lo[0] = xl; sa.n4[0] = Mtot*Dc/4;
    sa.src[1] = Wq; sa.hi[1] = wh + 0*(size_t)Dc*Dc; sa.lo[1] = wl + 0*(size_t)Dc*Dc; sa.n4[1] = Dc*Dc/4;
    sa.src[2] = Wv; sa.hi[2] = wh + 1*(size_t)Dc*Dc; sa.lo[2] = wl + 1*(size_t)Dc*Dc; sa.n4[2] = Dc*Dc/4;
    sa.src[3] = Wg; sa.hi[3] = wh + 2*(size_t)Dc*Dc; sa.lo[3] = wl + 2*(size_t)Dc*Dc; sa.n4[3] = Dc*Dc/4;
    sa.src[4] = Wo; sa.hi[4] = wh + 3*(size_t)Dc*Dc; sa.lo[4] = wl + 3*(size_t)Dc*Dc; sa.n4[4] = Dc*Dc/4;
    dim3 sgrid((Mtot*Dc/4 + 255)/256, 5);
    split_kernel<<<sgrid, 256>>>(sa);

    // Fused q/v/g projection GEMMs (z-indexed)
    GemmArgs a1;
    a1.Ah = xh; a1.Al = xl;
    a1.Wh[0] = wh + 0*(size_t)Dc*Dc; a1.Wl[0] = wl + 0*(size_t)Dc*Dc; a1.C[0] = q;
    a1.Wh[1] = wh + 1*(size_t)Dc*Dc; a1.Wl[1] = wl + 1*(size_t)Dc*Dc; a1.C[1] = v;
    a1.Wh[2] = wh + 2*(size_t)Dc*Dc; a1.Wl[2] = wl + 2*(size_t)Dc*Dc; a1.C[2] = g;
    dim3 grid_qvg(Dc/NT, Mtot/MT, 3);   // (8, 128, 3)
    gemm_mma<<<grid_qvg, 256, GEMM_SMEM>>>(a1);

    scan_pass1<<<Bc*Hc*NC, 64>>>(v, beta);
    scan_pass2<<<(Bc*Hc*Dhc)/256, 256>>>(beta);
    scan_pass3<<<Bc*Hc*NC, 64>>>(v, q, beta);   // q now holds ret

    ln_gate_kernel<<<Mtot, 256>>>(q, g, gamma, lbeta, zh, zl);

    // Output GEMM
    GemmArgs a2;
    a2.Ah = zh; a2.Al = zl;
    a2.Wh[0] = wh + 3*(size_t)Dc*Dc; a2.Wl[0] = wl + 3*(size_t)Dc*Dc; a2.C[0] = out;
    a2.Wh[1] = a2.Wh[0]; a2.Wl[1] = a2.Wl[0]; a2.C[1] = out;
    a2.Wh[2] = a2.Wh[0]; a2.Wl[2] = a2.Wl[0]; a2.C[2] = out;
    dim3 grid_o(Dc/NT, Mtot/MT, 1);     // (8, 128, 1)
    gemm_mma<<<grid_o, 256, GEMM_SMEM>>>(a2);
}